// round 1
// baseline (speedup 1.0000x reference)
#include <cuda_runtime.h>
#include <math.h>

// Problem constants
#define DIMC   768
#define NHEADS 12
#define HD     64
#define BATCH  16
#define SEQ    596
#define ROWS   (BATCH*SEQ)      // 9536
#define QKVC   2304
#define HIDDEN 3072
#define CLSK   20

// ---------------- scratch (static device globals; no allocation allowed) ----
__device__ float g_h1 [ROWS*DIMC];     // LN output (reused for LN1 and LN2)
__device__ float g_qkv[ROWS*QKVC];     // qkv projection
__device__ float g_oc [ROWS*DIMC];     // concatenated attention heads
__device__ float g_x2 [ROWS*DIMC];     // x + attn_out (residual 1)
__device__ float g_mlp[ROWS*HIDDEN];   // gelu(fc1) activations

// ---------------- LayerNorm: one block per row --------------------------------
__global__ void ln_kernel(const float* __restrict__ x,
                          const float* __restrict__ g,
                          const float* __restrict__ b,
                          float* __restrict__ out) {
    int row = blockIdx.x;
    const float* xr = x + (long long)row * DIMC;
    float s = 0.f, s2 = 0.f;
    for (int i = threadIdx.x; i < DIMC; i += blockDim.x) {
        float v = xr[i];
        s += v; s2 += v * v;
    }
    for (int o = 16; o; o >>= 1) {
        s  += __shfl_xor_sync(0xffffffffu, s,  o);
        s2 += __shfl_xor_sync(0xffffffffu, s2, o);
    }
    __shared__ float rs[8], rs2[8];
    int wid = threadIdx.x >> 5, lid = threadIdx.x & 31;
    if (lid == 0) { rs[wid] = s; rs2[wid] = s2; }
    __syncthreads();
    if (threadIdx.x == 0) {
        float a = 0.f, a2 = 0.f;
        for (int i = 0; i < (int)(blockDim.x >> 5); i++) { a += rs[i]; a2 += rs2[i]; }
        rs[0] = a; rs2[0] = a2;
    }
    __syncthreads();
    float mean = rs[0] * (1.0f / DIMC);
    float var  = rs2[0] * (1.0f / DIMC) - mean * mean;
    float inv  = rsqrtf(var + 1e-5f);
    float* orow = out + (long long)row * DIMC;
    for (int i = threadIdx.x; i < DIMC; i += blockDim.x)
        orow[i] = (xr[i] - mean) * inv * g[i] + b[i];
}

// ---------------- Tiled SGEMM, C = act(alpha * A @ B^T + bias) [+ res] --------
// A: [M,K] lda, B: [N,K] ldb (transposed access), C: [M,N] ldc.
// Batched via gridDim.z: offsets = (z/NHEADS)*s?b + (z%NHEADS)*s?h.
// act: 0 = none, 1 = exact GELU. res (if non-null) is [M,N] with ldc (batch-1 only).
#define BM 64
#define BN 64
#define BK 16

__global__ void gemm_tn(const float* __restrict__ A, const float* __restrict__ Bm,
                        const float* __restrict__ bias, const float* __restrict__ res,
                        float* __restrict__ C,
                        int M, int Nn, int K, int lda, int ldb, int ldc,
                        long long sAb, long long sAh, long long sBb, long long sBh,
                        long long sCb, long long sCh,
                        float alpha, int act) {
    int z  = blockIdx.z;
    int zb = z / NHEADS, zh = z % NHEADS;
    A  += zb * sAb + zh * sAh;
    Bm += zb * sBb + zh * sBh;
    C  += zb * sCb + zh * sCh;

    __shared__ __align__(16) float As[BK][BM];
    __shared__ __align__(16) float Bs[BK][BN];

    int tx = threadIdx.x & 15, ty = threadIdx.x >> 4;
    int row0 = blockIdx.y * BM, col0 = blockIdx.x * BN;
    float acc[4][4] = {};

    for (int k0 = 0; k0 < K; k0 += BK) {
        for (int i = threadIdx.x; i < BM * BK; i += 256) {
            int r = i >> 4, c = i & 15;
            int gr = row0 + r, gc = k0 + c;
            As[c][r] = (gr < M && gc < K) ? A[(long long)gr * lda + gc] : 0.f;
        }
        for (int i = threadIdx.x; i < BN * BK; i += 256) {
            int r = i >> 4, c = i & 15;
            int gr = col0 + r, gc = k0 + c;
            Bs[c][r] = (gr < Nn && gc < K) ? Bm[(long long)gr * ldb + gc] : 0.f;
        }
        __syncthreads();
        #pragma unroll
        for (int kk = 0; kk < BK; kk++) {
            float4 a4 = *(const float4*)&As[kk][ty * 4];
            float4 b4 = *(const float4*)&Bs[kk][tx * 4];
            float a[4] = {a4.x, a4.y, a4.z, a4.w};
            float b[4] = {b4.x, b4.y, b4.z, b4.w};
            #pragma unroll
            for (int i = 0; i < 4; i++)
                #pragma unroll
                for (int j = 0; j < 4; j++)
                    acc[i][j] += a[i] * b[j];
        }
        __syncthreads();
    }

    #pragma unroll
    for (int i = 0; i < 4; i++) {
        int gr = row0 + ty * 4 + i;
        if (gr >= M) continue;
        #pragma unroll
        for (int j = 0; j < 4; j++) {
            int gc = col0 + tx * 4 + j;
            if (gc >= Nn) continue;
            float v = acc[i][j] * alpha;
            if (bias) v += bias[gc];
            if (act == 1) v = 0.5f * v * (1.0f + erff(v * 0.70710678118654752f));
            if (res) v += res[(long long)gr * ldc + gc];
            C[(long long)gr * ldc + gc] = v;
        }
    }
}

// ---------------- Tiled SGEMM NN variant: C = A @ B  (for attn @ V) -----------
__global__ void gemm_nn(const float* __restrict__ A, const float* __restrict__ Bm,
                        float* __restrict__ C,
                        int M, int Nn, int K, int lda, int ldb, int ldc,
                        long long sAb, long long sAh, long long sBb, long long sBh,
                        long long sCb, long long sCh) {
    int z  = blockIdx.z;
    int zb = z / NHEADS, zh = z % NHEADS;
    A  += zb * sAb + zh * sAh;
    Bm += zb * sBb + zh * sBh;
    C  += zb * sCb + zh * sCh;

    __shared__ __align__(16) float As[BK][BM];
    __shared__ __align__(16) float Bs[BK][BN];

    int tx = threadIdx.x & 15, ty = threadIdx.x >> 4;
    int row0 = blockIdx.y * BM, col0 = blockIdx.x * BN;
    float acc[4][4] = {};

    for (int k0 = 0; k0 < K; k0 += BK) {
        for (int i = threadIdx.x; i < BM * BK; i += 256) {
            int r = i >> 4, c = i & 15;
            int gr = row0 + r, gc = k0 + c;
            As[c][r] = (gr < M && gc < K) ? A[(long long)gr * lda + gc] : 0.f;
        }
        for (int i = threadIdx.x; i < BK * BN; i += 256) {
            int kk = i >> 6, c = i & 63;
            int gk = k0 + kk, gc = col0 + c;
            Bs[kk][c] = (gk < K && gc < Nn) ? Bm[(long long)gk * ldb + gc] : 0.f;
        }
        __syncthreads();
        #pragma unroll
        for (int kk = 0; kk < BK; kk++) {
            float4 a4 = *(const float4*)&As[kk][ty * 4];
            float4 b4 = *(const float4*)&Bs[kk][tx * 4];
            float a[4] = {a4.x, a4.y, a4.z, a4.w};
            float b[4] = {b4.x, b4.y, b4.z, b4.w};
            #pragma unroll
            for (int i = 0; i < 4; i++)
                #pragma unroll
                for (int j = 0; j < 4; j++)
                    acc[i][j] += a[i] * b[j];
        }
        __syncthreads();
    }

    #pragma unroll
    for (int i = 0; i < 4; i++) {
        int gr = row0 + ty * 4 + i;
        if (gr >= M) continue;
        #pragma unroll
        for (int j = 0; j < 4; j++) {
            int gc = col0 + tx * 4 + j;
            if (gc >= Nn) continue;
            C[(long long)gr * ldc + gc] = acc[i][j];
        }
    }
}

// ---------------- Split softmax, in place: [0,CLSK) and [CLSK,SEQ) ------------
__device__ __forceinline__ float blkMax(float v) {
    for (int o = 16; o; o >>= 1) v = fmaxf(v, __shfl_xor_sync(0xffffffffu, v, o));
    __shared__ float s[8];
    int w = threadIdx.x >> 5, l = threadIdx.x & 31;
    if (l == 0) s[w] = v;
    __syncthreads();
    if (threadIdx.x < 8) {
        float t = s[threadIdx.x];
        for (int o = 4; o; o >>= 1) t = fmaxf(t, __shfl_xor_sync(0xffu, t, o));
        if (threadIdx.x == 0) s[0] = t;
    }
    __syncthreads();
    float r = s[0];
    __syncthreads();
    return r;
}
__device__ __forceinline__ float blkSum(float v) {
    for (int o = 16; o; o >>= 1) v += __shfl_xor_sync(0xffffffffu, v, o);
    __shared__ float s[8];
    int w = threadIdx.x >> 5, l = threadIdx.x & 31;
    if (l == 0) s[w] = v;
    __syncthreads();
    if (threadIdx.x < 8) {
        float t = s[threadIdx.x];
        for (int o = 4; o; o >>= 1) t += __shfl_xor_sync(0xffu, t, o);
        if (threadIdx.x == 0) s[0] = t;
    }
    __syncthreads();
    float r = s[0];
    __syncthreads();
    return r;
}

__global__ void softmax_split(float* __restrict__ w) {
    float* p = w + (long long)blockIdx.x * SEQ;
    int tid = threadIdx.x;

    // segment 1: [0, CLSK)
    float m = -1e30f;
    for (int i = tid; i < CLSK; i += 256) m = fmaxf(m, p[i]);
    m = blkMax(m);
    float s = 0.f;
    for (int i = tid; i < CLSK; i += 256) { float e = expf(p[i] - m); p[i] = e; s += e; }
    s = blkSum(s);
    float r = 1.0f / s;
    for (int i = tid; i < CLSK; i += 256) p[i] *= r;

    // segment 2: [CLSK, SEQ)
    m = -1e30f;
    for (int i = CLSK + tid; i < SEQ; i += 256) m = fmaxf(m, p[i]);
    m = blkMax(m);
    s = 0.f;
    for (int i = CLSK + tid; i < SEQ; i += 256) { float e = expf(p[i] - m); p[i] = e; s += e; }
    s = blkSum(s);
    r = 1.0f / s;
    for (int i = CLSK + tid; i < SEQ; i += 256) p[i] *= r;
}

// ---------------- host-side orchestration -------------------------------------
extern "C" void kernel_launch(void* const* d_in, const int* in_sizes, int n_in,
                              void* d_out, int out_size) {
    const float* x      = (const float*)d_in[0];
    const float* qkv_w  = (const float*)d_in[1];
    const float* qkv_b  = (const float*)d_in[2];
    const float* proj_w = (const float*)d_in[3];
    const float* proj_b = (const float*)d_in[4];
    const float* ln1_g  = (const float*)d_in[5];
    const float* ln1_b  = (const float*)d_in[6];
    const float* ln2_g  = (const float*)d_in[7];
    const float* ln2_b  = (const float*)d_in[8];
    const float* fc1_w  = (const float*)d_in[9];
    const float* fc1_b  = (const float*)d_in[10];
    const float* fc2_w  = (const float*)d_in[11];
    const float* fc2_b  = (const float*)d_in[12];

    float* out_x = (float*)d_out;                                   // [16,596,768]
    float* out_w = out_x + (long long)ROWS * DIMC;                  // [16,12,596,596]

    float *h1, *qkv, *oc, *x2, *mlp;
    cudaGetSymbolAddress((void**)&h1,  g_h1);
    cudaGetSymbolAddress((void**)&qkv, g_qkv);
    cudaGetSymbolAddress((void**)&oc,  g_oc);
    cudaGetSymbolAddress((void**)&x2,  g_x2);
    cudaGetSymbolAddress((void**)&mlp, g_mlp);

    const long long sQb = (long long)SEQ * QKVC;       // per-batch stride in qkv
    const long long sWb = (long long)NHEADS * SEQ * SEQ;
    const long long sWh = (long long)SEQ * SEQ;
    const long long sOb = (long long)SEQ * DIMC;

    // 1. LN1
    ln_kernel<<<ROWS, 256>>>(x, ln1_g, ln1_b, h1);

    // 2. QKV projection: [9536,768] @ [2304,768]^T -> [9536,2304]
    gemm_tn<<<dim3(QKVC / BN, ROWS / BM, 1), 256>>>(
        h1, qkv_w, qkv_b, nullptr, qkv,
        ROWS, QKVC, DIMC, DIMC, DIMC, QKVC,
        0, 0, 0, 0, 0, 0, 1.0f, 0);

    // 3. S = (Q @ K^T) * scale, per (b,h), written straight into weights output
    gemm_tn<<<dim3((SEQ + BN - 1) / BN, (SEQ + BM - 1) / BM, BATCH * NHEADS), 256>>>(
        qkv /*Q*/, qkv + DIMC /*K*/, nullptr, nullptr, out_w,
        SEQ, SEQ, HD, QKVC, QKVC, SEQ,
        sQb, HD, sQb, HD, sWb, sWh, 0.125f, 0);

    // 4. split softmax in place (this IS the weights output)
    softmax_split<<<BATCH * NHEADS * SEQ, 256>>>(out_w);

    // 5. O = attn @ V per (b,h), scattered into [B,N,768] head-concat layout
    gemm_nn<<<dim3(1, (SEQ + BM - 1) / BM, BATCH * NHEADS), 256>>>(
        out_w, qkv + 2 * DIMC /*V*/, oc,
        SEQ, HD, SEQ, SEQ, QKVC, DIMC,
        sWb, sWh, sQb, HD, sOb, HD);

    // 6. proj + residual: x2 = x + O @ proj_w^T + proj_b
    gemm_tn<<<dim3(DIMC / BN, ROWS / BM, 1), 256>>>(
        oc, proj_w, proj_b, x, x2,
        ROWS, DIMC, DIMC, DIMC, DIMC, DIMC,
        0, 0, 0, 0, 0, 0, 1.0f, 0);

    // 7. LN2
    ln_kernel<<<ROWS, 256>>>(x2, ln2_g, ln2_b, h1);

    // 8. FC1 + exact GELU
    gemm_tn<<<dim3(HIDDEN / BN, ROWS / BM, 1), 256>>>(
        h1, fc1_w, fc1_b, nullptr, mlp,
        ROWS, HIDDEN, DIMC, DIMC, DIMC, HIDDEN,
        0, 0, 0, 0, 0, 0, 1.0f, 1);

    // 9. FC2 + residual -> final x output
    gemm_tn<<<dim3(DIMC / BN, ROWS / BM, 1), 256>>>(
        mlp, fc2_w, fc2_b, x2, out_x,
        ROWS, DIMC, HIDDEN, HIDDEN, HIDDEN, DIMC,
        0, 0, 0, 0, 0, 0, 1.0f, 0);
}

// round 2
// speedup vs baseline: 3.8956x; 3.8956x over previous
#include <cuda_runtime.h>
#include <math.h>

// Problem constants
#define DIMC   768
#define NHEADS 12
#define HD     64
#define BATCH  16
#define SEQ    596
#define ROWS   (BATCH*SEQ)      // 9536
#define QKVC   2304
#define HIDDEN 3072
#define CLSK   20

// ---------------- scratch (static device globals; no allocation allowed) ----
__device__ float g_h1 [ROWS*DIMC];     // LN output (reused for LN1 and LN2)
__device__ float g_qkv[ROWS*QKVC];     // qkv projection
__device__ float g_oc [ROWS*DIMC];     // concatenated attention heads
__device__ float g_x2 [ROWS*DIMC];     // x + attn_out (residual 1)
__device__ float g_mlp[ROWS*HIDDEN];   // gelu(fc1) activations

// ---------------- LayerNorm: one block per row --------------------------------
__global__ void ln_kernel(const float* __restrict__ x,
                          const float* __restrict__ g,
                          const float* __restrict__ b,
                          float* __restrict__ out) {
    int row = blockIdx.x;
    const float* xr = x + (long long)row * DIMC;
    float s = 0.f, s2 = 0.f;
    for (int i = threadIdx.x; i < DIMC; i += blockDim.x) {
        float v = xr[i];
        s += v; s2 += v * v;
    }
    for (int o = 16; o; o >>= 1) {
        s  += __shfl_xor_sync(0xffffffffu, s,  o);
        s2 += __shfl_xor_sync(0xffffffffu, s2, o);
    }
    __shared__ float rs[8], rs2[8];
    int wid = threadIdx.x >> 5, lid = threadIdx.x & 31;
    if (lid == 0) { rs[wid] = s; rs2[wid] = s2; }
    __syncthreads();
    if (threadIdx.x == 0) {
        float a = 0.f, a2 = 0.f;
        for (int i = 0; i < (int)(blockDim.x >> 5); i++) { a += rs[i]; a2 += rs2[i]; }
        rs[0] = a; rs2[0] = a2;
    }
    __syncthreads();
    float mean = rs[0] * (1.0f / DIMC);
    float var  = rs2[0] * (1.0f / DIMC) - mean * mean;
    float inv  = rsqrtf(var + 1e-5f);
    float* orow = out + (long long)row * DIMC;
    for (int i = threadIdx.x; i < DIMC; i += blockDim.x)
        orow[i] = (xr[i] - mean) * inv * g[i] + b[i];
}

// ---------------- TF32 tensor-core GEMM ---------------------------------------
// C = act(alpha * A @ op(B) + bias) [+ res]
// A: [M,K] row-major (lda). transB=0: B [N,K] row-major (ldb) -> C=A@B^T.
//                           transB=1: B [K,N] row-major (ldb) -> C=A@B.
// Batched over gridDim.z: offsets = (z/NHEADS)*s?b + (z%NHEADS)*s?h.
// act: 0 none, 1 exact GELU. res (ldc layout) added post-activation.
#define BM 128
#define BN 128
#define BKT 32
#define SPAD 36   // smem row stride (words); (4m+k)%32 distinct -> conflict-free frags

__device__ __forceinline__ unsigned f2tf(float f) {
    unsigned u;
    asm("cvt.rna.tf32.f32 %0, %1;" : "=r"(u) : "f"(f));
    return u;
}

__device__ __forceinline__ void mma8(float* c, const unsigned* a, const unsigned* b) {
    asm volatile(
        "mma.sync.aligned.m16n8k8.row.col.f32.tf32.tf32.f32 "
        "{%0,%1,%2,%3}, {%4,%5,%6,%7}, {%8,%9}, {%0,%1,%2,%3};"
        : "+f"(c[0]), "+f"(c[1]), "+f"(c[2]), "+f"(c[3])
        : "r"(a[0]), "r"(a[1]), "r"(a[2]), "r"(a[3]), "r"(b[0]), "r"(b[1]));
}

__global__ __launch_bounds__(256)
void gemm_tc(const float* __restrict__ A, const float* __restrict__ B,
             const float* __restrict__ bias, const float* __restrict__ res,
             float* __restrict__ C,
             int M, int Nn, int K, int lda, int ldb, int ldc,
             long long sAb, long long sAh, long long sBb, long long sBh,
             long long sCb, long long sCh,
             float alpha, int act, int transB) {
    int z  = blockIdx.z;
    int zb = z / NHEADS, zh = z % NHEADS;
    A += zb * sAb + zh * sAh;
    B += zb * sBb + zh * sBh;
    C += zb * sCb + zh * sCh;

    __shared__ unsigned As[BM][SPAD];
    __shared__ unsigned Bs[BN][SPAD];

    int tid   = threadIdx.x;
    int warp  = tid >> 5, lane = tid & 31;
    int wm    = warp >> 2;      // 0..1  (64-row strip)
    int wn    = warp & 3;       // 0..3  (32-col strip)
    int group = lane >> 2;      // 0..7
    int tg    = lane & 3;       // 0..3

    int row0 = blockIdx.y * BM;
    int col0 = blockIdx.x * BN;

    float acc[4][4][4];
    #pragma unroll
    for (int i = 0; i < 4; i++)
        #pragma unroll
        for (int j = 0; j < 4; j++)
            #pragma unroll
            for (int r = 0; r < 4; r++) acc[i][j][r] = 0.f;

    for (int k0 = 0; k0 < K; k0 += BKT) {
        // ---- load A tile: 128 x 32, float4 per thread x4 ----
        #pragma unroll
        for (int t = 0; t < 4; t++) {
            int i = tid + t * 256;
            int r = i >> 3;
            int c = (i & 7) << 2;
            int gr = row0 + r, gk = k0 + c;
            float4 v4 = make_float4(0.f, 0.f, 0.f, 0.f);
            if (gr < M && gk < K)   // K always %4==0 here
                v4 = *(const float4*)(A + (long long)gr * lda + gk);
            As[r][c]     = f2tf(v4.x);
            As[r][c + 1] = f2tf(v4.y);
            As[r][c + 2] = f2tf(v4.z);
            As[r][c + 3] = f2tf(v4.w);
        }
        // ---- load B tile -> Bs[n][k] ----
        if (!transB) {
            #pragma unroll
            for (int t = 0; t < 4; t++) {
                int i = tid + t * 256;
                int r = i >> 3;
                int c = (i & 7) << 2;
                int gn = col0 + r, gk = k0 + c;
                float4 v4 = make_float4(0.f, 0.f, 0.f, 0.f);
                if (gn < Nn && gk < K)
                    v4 = *(const float4*)(B + (long long)gn * ldb + gk);
                Bs[r][c]     = f2tf(v4.x);
                Bs[r][c + 1] = f2tf(v4.y);
                Bs[r][c + 2] = f2tf(v4.z);
                Bs[r][c + 3] = f2tf(v4.w);
            }
        } else {
            #pragma unroll
            for (int t = 0; t < 16; t++) {
                int i = tid + t * 256;
                int k = i >> 7;        // 0..31
                int n = i & 127;
                int gk = k0 + k, gn = col0 + n;
                float vv = (gk < K && gn < Nn) ? B[(long long)gk * ldb + gn] : 0.f;
                Bs[n][k] = f2tf(vv);
            }
        }
        __syncthreads();

        // ---- compute: 4 k-steps of 8 ----
        #pragma unroll
        for (int ks = 0; ks < 4; ks++) {
            int kb = ks * 8;
            unsigned a[4][4], b[4][2];
            #pragma unroll
            for (int mt = 0; mt < 4; mt++) {
                int m = wm * 64 + mt * 16 + group;
                a[mt][0] = As[m][kb + tg];
                a[mt][1] = As[m + 8][kb + tg];
                a[mt][2] = As[m][kb + tg + 4];
                a[mt][3] = As[m + 8][kb + tg + 4];
            }
            #pragma unroll
            for (int nt = 0; nt < 4; nt++) {
                int n = wn * 32 + nt * 8 + group;
                b[nt][0] = Bs[n][kb + tg];
                b[nt][1] = Bs[n][kb + tg + 4];
            }
            #pragma unroll
            for (int mt = 0; mt < 4; mt++)
                #pragma unroll
                for (int nt = 0; nt < 4; nt++)
                    mma8(acc[mt][nt], a[mt], b[nt]);
        }
        __syncthreads();
    }

    // ---- epilogue ----
    #pragma unroll
    for (int mt = 0; mt < 4; mt++) {
        #pragma unroll
        for (int nt = 0; nt < 4; nt++) {
            int gm0 = row0 + wm * 64 + mt * 16 + group;
            int gn0 = col0 + wn * 32 + nt * 8 + tg * 2;
            float* cr = acc[mt][nt];
            #pragma unroll
            for (int rr = 0; rr < 2; rr++) {
                int gm = gm0 + rr * 8;
                if (gm >= M) continue;
                #pragma unroll
                for (int cc = 0; cc < 2; cc++) {
                    int gn = gn0 + cc;
                    if (gn >= Nn) continue;
                    float vv = cr[rr * 2 + cc] * alpha;
                    if (bias) vv += bias[gn];
                    if (act == 1) vv = 0.5f * vv * (1.0f + erff(vv * 0.70710678118654752f));
                    if (res) vv += res[(long long)gm * ldc + gn];
                    C[(long long)gm * ldc + gn] = vv;
                }
            }
        }
    }
}

// ---------------- Split softmax, warp-per-row, single pass --------------------
__global__ void softmax_split(float* __restrict__ w) {
    long long row = (long long)blockIdx.x * 8 + (threadIdx.x >> 5);
    int lane = threadIdx.x & 31;
    float* p = w + row * SEQ;

    float v[19];
    #pragma unroll
    for (int j = 0; j < 19; j++) {
        int i = lane + j * 32;
        v[j] = (i < SEQ) ? p[i] : -1e30f;
    }
    bool in0 = lane < CLSK;   // seg0 lives entirely in v[0], lanes 0..19

    float m0 = in0 ? v[0] : -1e30f;
    float m1 = in0 ? -1e30f : v[0];
    #pragma unroll
    for (int j = 1; j < 19; j++) m1 = fmaxf(m1, v[j]);
    #pragma unroll
    for (int o = 16; o; o >>= 1) {
        m0 = fmaxf(m0, __shfl_xor_sync(0xffffffffu, m0, o));
        m1 = fmaxf(m1, __shfl_xor_sync(0xffffffffu, m1, o));
    }

    float s0 = 0.f, s1 = 0.f;
    {
        float e = expf(v[0] - (in0 ? m0 : m1));
        v[0] = e;
        if (in0) s0 += e; else s1 += e;
    }
    #pragma unroll
    for (int j = 1; j < 19; j++) {
        int i = lane + j * 32;
        float e = (i < SEQ) ? expf(v[j] - m1) : 0.f;
        v[j] = e; s1 += e;
    }
    #pragma unroll
    for (int o = 16; o; o >>= 1) {
        s0 += __shfl_xor_sync(0xffffffffu, s0, o);
        s1 += __shfl_xor_sync(0xffffffffu, s1, o);
    }
    float r0 = 1.0f / s0, r1 = 1.0f / s1;

    p[lane] = v[0] * (in0 ? r0 : r1);
    #pragma unroll
    for (int j = 1; j < 19; j++) {
        int i = lane + j * 32;
        if (i < SEQ) p[i] = v[j] * r1;
    }
}

// ---------------- host-side orchestration -------------------------------------
extern "C" void kernel_launch(void* const* d_in, const int* in_sizes, int n_in,
                              void* d_out, int out_size) {
    const float* x      = (const float*)d_in[0];
    const float* qkv_w  = (const float*)d_in[1];
    const float* qkv_b  = (const float*)d_in[2];
    const float* proj_w = (const float*)d_in[3];
    const float* proj_b = (const float*)d_in[4];
    const float* ln1_g  = (const float*)d_in[5];
    const float* ln1_b  = (const float*)d_in[6];
    const float* ln2_g  = (const float*)d_in[7];
    const float* ln2_b  = (const float*)d_in[8];
    const float* fc1_w  = (const float*)d_in[9];
    const float* fc1_b  = (const float*)d_in[10];
    const float* fc2_w  = (const float*)d_in[11];
    const float* fc2_b  = (const float*)d_in[12];

    float* out_x = (float*)d_out;                                   // [16,596,768]
    float* out_w = out_x + (long long)ROWS * DIMC;                  // [16,12,596,596]

    float *h1, *qkv, *oc, *x2, *mlp;
    cudaGetSymbolAddress((void**)&h1,  g_h1);
    cudaGetSymbolAddress((void**)&qkv, g_qkv);
    cudaGetSymbolAddress((void**)&oc,  g_oc);
    cudaGetSymbolAddress((void**)&x2,  g_x2);
    cudaGetSymbolAddress((void**)&mlp, g_mlp);

    const long long sQb = (long long)SEQ * QKVC;
    const long long sWb = (long long)NHEADS * SEQ * SEQ;
    const long long sWh = (long long)SEQ * SEQ;
    const long long sOb = (long long)SEQ * DIMC;

    const int MB = (ROWS + BM - 1) / BM;   // 75
    const int SB = (SEQ + BM - 1) / BM;    // 5

    // 1. LN1
    ln_kernel<<<ROWS, 256>>>(x, ln1_g, ln1_b, h1);

    // 2. QKV projection: [9536,768] @ [2304,768]^T -> [9536,2304]
    gemm_tc<<<dim3(QKVC / BN, MB, 1), 256>>>(
        h1, qkv_w, qkv_b, nullptr, qkv,
        ROWS, QKVC, DIMC, DIMC, DIMC, QKVC,
        0, 0, 0, 0, 0, 0, 1.0f, 0, 0);

    // 3. S = (Q @ K^T) * scale, per (b,h), straight into weights output
    gemm_tc<<<dim3(SB, SB, BATCH * NHEADS), 256>>>(
        qkv /*Q*/, qkv + DIMC /*K*/, nullptr, nullptr, out_w,
        SEQ, SEQ, HD, QKVC, QKVC, SEQ,
        sQb, HD, sQb, HD, sWb, sWh, 0.125f, 0, 0);

    // 4. split softmax in place (this IS the weights output)
    softmax_split<<<(BATCH * NHEADS * SEQ) / 8, 256>>>(out_w);

    // 5. O = attn @ V per (b,h)  (NN: B is [K=SEQ, N=HD] with row stride QKVC)
    gemm_tc<<<dim3(1, SB, BATCH * NHEADS), 256>>>(
        out_w, qkv + 2 * DIMC /*V*/, nullptr, nullptr, oc,
        SEQ, HD, SEQ, SEQ, QKVC, DIMC,
        sWb, sWh, sQb, HD, sOb, HD, 1.0f, 0, 1);

    // 6. proj + residual: x2 = x + O @ proj_w^T + proj_b
    gemm_tc<<<dim3(DIMC / BN, MB, 1), 256>>>(
        oc, proj_w, proj_b, x, x2,
        ROWS, DIMC, DIMC, DIMC, DIMC, DIMC,
        0, 0, 0, 0, 0, 0, 1.0f, 0, 0);

    // 7. LN2
    ln_kernel<<<ROWS, 256>>>(x2, ln2_g, ln2_b, h1);

    // 8. FC1 + exact GELU
    gemm_tc<<<dim3(HIDDEN / BN, MB, 1), 256>>>(
        h1, fc1_w, fc1_b, nullptr, mlp,
        ROWS, HIDDEN, DIMC, DIMC, DIMC, HIDDEN,
        0, 0, 0, 0, 0, 0, 1.0f, 1, 0);

    // 9. FC2 + residual -> final x output
    gemm_tc<<<dim3(DIMC / BN, MB, 1), 256>>>(
        mlp, fc2_w, fc2_b, x2, out_x,
        ROWS, DIMC, HIDDEN, HIDDEN, HIDDEN, DIMC,
        0, 0, 0, 0, 0, 0, 1.0f, 0, 0);
}

// round 3
// speedup vs baseline: 5.3921x; 1.3841x over previous
#include <cuda_runtime.h>
#include <math.h>

// Problem constants
#define DIMC   768
#define NHEADS 12
#define HD     64
#define BATCH  16
#define SEQ    596
#define ROWS   (BATCH*SEQ)      // 9536
#define QKVC   2304
#define HIDDEN 3072
#define CLSK   20

// ---------------- scratch (static device globals; no allocation allowed) ----
__device__ float g_h1 [ROWS*DIMC];
__device__ float g_qkv[ROWS*QKVC];
__device__ float g_oc [ROWS*DIMC];
__device__ float g_x2 [ROWS*DIMC];
__device__ float g_mlp[ROWS*HIDDEN];

// ---------------- LayerNorm: one block per row --------------------------------
__global__ void ln_kernel(const float* __restrict__ x,
                          const float* __restrict__ g,
                          const float* __restrict__ b,
                          float* __restrict__ out) {
    int row = blockIdx.x;
    const float* xr = x + (long long)row * DIMC;
    float s = 0.f, s2 = 0.f;
    for (int i = threadIdx.x; i < DIMC; i += blockDim.x) {
        float v = xr[i];
        s += v; s2 += v * v;
    }
    for (int o = 16; o; o >>= 1) {
        s  += __shfl_xor_sync(0xffffffffu, s,  o);
        s2 += __shfl_xor_sync(0xffffffffu, s2, o);
    }
    __shared__ float rs[8], rs2[8];
    int wid = threadIdx.x >> 5, lid = threadIdx.x & 31;
    if (lid == 0) { rs[wid] = s; rs2[wid] = s2; }
    __syncthreads();
    if (threadIdx.x == 0) {
        float a = 0.f, a2 = 0.f;
        for (int i = 0; i < (int)(blockDim.x >> 5); i++) { a += rs[i]; a2 += rs2[i]; }
        rs[0] = a; rs2[0] = a2;
    }
    __syncthreads();
    float mean = rs[0] * (1.0f / DIMC);
    float var  = rs2[0] * (1.0f / DIMC) - mean * mean;
    float inv  = rsqrtf(var + 1e-5f);
    float* orow = out + (long long)row * DIMC;
    for (int i = threadIdx.x; i < DIMC; i += blockDim.x)
        orow[i] = (xr[i] - mean) * inv * g[i] + b[i];
}

// ---------------- TF32 tensor-core GEMM, 3-stage cp.async pipeline ------------
// C = act(alpha * A @ op(B) + bias) [+ res]
// A [M,K] row-major. transB=0: B [N,K] -> C=A@B^T. transB=1: B [K,N] -> C=A@B.
#define BM 128
#define BN 128
#define BKT 32
#define SPAD 36
#define STAGES 3
#define STAGE_W ((BM + BN) * SPAD)
#define GEMM_SMEM (STAGES * STAGE_W * 4)

__device__ __forceinline__ void mma8(float* c, const unsigned* a, const unsigned* b) {
    asm volatile(
        "mma.sync.aligned.m16n8k8.row.col.f32.tf32.tf32.f32 "
        "{%0,%1,%2,%3}, {%4,%5,%6,%7}, {%8,%9}, {%0,%1,%2,%3};"
        : "+f"(c[0]), "+f"(c[1]), "+f"(c[2]), "+f"(c[3])
        : "r"(a[0]), "r"(a[1]), "r"(a[2]), "r"(a[3]), "r"(b[0]), "r"(b[1]));
}

__device__ __forceinline__ void ldgsts16(unsigned* dst, const float* src, bool pred) {
    unsigned sa = (unsigned)__cvta_generic_to_shared(dst);
    unsigned ssz = pred ? 16u : 0u;
    asm volatile("cp.async.cg.shared.global [%0], [%1], 16, %2;"
                 :: "r"(sa), "l"(src), "r"(ssz));
}
__device__ __forceinline__ void ldgsts4(unsigned* dst, const float* src, bool pred) {
    unsigned sa = (unsigned)__cvta_generic_to_shared(dst);
    unsigned ssz = pred ? 4u : 0u;
    asm volatile("cp.async.ca.shared.global [%0], [%1], 4, %2;"
                 :: "r"(sa), "l"(src), "r"(ssz));
}
__device__ __forceinline__ void cp_commit() {
    asm volatile("cp.async.commit_group;");
}

__global__ __launch_bounds__(256)
void gemm_tc(const float* __restrict__ A, const float* __restrict__ B,
             const float* __restrict__ bias, const float* __restrict__ res,
             float* __restrict__ C,
             int M, int Nn, int K, int lda, int ldb, int ldc,
             long long sAb, long long sAh, long long sBb, long long sBh,
             long long sCb, long long sCh,
             float alpha, int act, int transB) {
    extern __shared__ unsigned sh[];

    int z  = blockIdx.z;
    int zb = z / NHEADS, zh = z % NHEADS;
    A += zb * sAb + zh * sAh;
    B += zb * sBb + zh * sBh;
    C += zb * sCb + zh * sCh;

    int tid   = threadIdx.x;
    int warp  = tid >> 5, lane = tid & 31;
    int wm    = warp >> 2;
    int wn    = warp & 3;
    int group = lane >> 2;
    int tg    = lane & 3;

    int row0 = blockIdx.y * BM;
    int col0 = blockIdx.x * BN;

    float acc[4][4][4];
    #pragma unroll
    for (int i = 0; i < 4; i++)
        #pragma unroll
        for (int j = 0; j < 4; j++)
            #pragma unroll
            for (int r = 0; r < 4; r++) acc[i][j][r] = 0.f;

    // ---- tile loader (async) ----
    auto load_tiles = [&](int stage, int k0) {
        unsigned* Asb = sh + stage * STAGE_W;
        unsigned* Bsb = Asb + BM * SPAD;
        #pragma unroll
        for (int t = 0; t < 4; t++) {
            int i = tid + t * 256;
            int r = i >> 3;
            int c = (i & 7) << 2;
            int gr = row0 + r, gk = k0 + c;
            bool p = (gr < M) && (gk + 4 <= K);
            const float* src = p ? (A + (long long)gr * lda + gk) : A;
            ldgsts16(Asb + r * SPAD + c, src, p);
        }
        if (!transB) {
            #pragma unroll
            for (int t = 0; t < 4; t++) {
                int i = tid + t * 256;
                int r = i >> 3;
                int c = (i & 7) << 2;
                int gn = col0 + r, gk = k0 + c;
                bool p = (gn < Nn) && (gk + 4 <= K);
                const float* src = p ? (B + (long long)gn * ldb + gk) : B;
                ldgsts16(Bsb + r * SPAD + c, src, p);
            }
        } else {
            #pragma unroll
            for (int t = 0; t < 16; t++) {
                int i = tid + t * 256;
                int k = i >> 7;
                int n = i & 127;
                int gk = k0 + k, gn = col0 + n;
                bool p = (gk < K) && (gn < Nn);
                const float* src = p ? (B + (long long)gk * ldb + gn) : B;
                ldgsts4(Bsb + n * SPAD + k, src, p);
            }
        }
    };

    auto compute = [&](int stage) {
        unsigned* Asb = sh + stage * STAGE_W;
        unsigned* Bsb = Asb + BM * SPAD;
        #pragma unroll
        for (int ks = 0; ks < 4; ks++) {
            int kb = ks * 8;
            unsigned a[4][4], b[4][2];
            #pragma unroll
            for (int mt = 0; mt < 4; mt++) {
                int m = wm * 64 + mt * 16 + group;
                a[mt][0] = Asb[m * SPAD + kb + tg];
                a[mt][1] = Asb[(m + 8) * SPAD + kb + tg];
                a[mt][2] = Asb[m * SPAD + kb + tg + 4];
                a[mt][3] = Asb[(m + 8) * SPAD + kb + tg + 4];
            }
            #pragma unroll
            for (int nt = 0; nt < 4; nt++) {
                int n = wn * 32 + nt * 8 + group;
                b[nt][0] = Bsb[n * SPAD + kb + tg];
                b[nt][1] = Bsb[n * SPAD + kb + tg + 4];
            }
            #pragma unroll
            for (int mt = 0; mt < 4; mt++)
                #pragma unroll
                for (int nt = 0; nt < 4; nt++)
                    mma8(acc[mt][nt], a[mt], b[nt]);
        }
    };

    int nT = (K + BKT - 1) / BKT;

    // prologue: prefetch STAGES-1 tiles
    #pragma unroll
    for (int s = 0; s < STAGES - 1; s++) {
        if (s < nT) load_tiles(s, s * BKT);
        cp_commit();
    }

    for (int t = 0; t < nT; t++) {
        int pf = t + STAGES - 1;
        if (pf < nT) load_tiles(pf % STAGES, pf * BKT);
        cp_commit();
        asm volatile("cp.async.wait_group %0;" :: "n"(STAGES - 1));
        __syncthreads();
        compute(t % STAGES);
        __syncthreads();
    }

    // ---- epilogue ----
    #pragma unroll
    for (int mt = 0; mt < 4; mt++) {
        #pragma unroll
        for (int nt = 0; nt < 4; nt++) {
            int gm0 = row0 + wm * 64 + mt * 16 + group;
            int gn0 = col0 + wn * 32 + nt * 8 + tg * 2;
            float* cr = acc[mt][nt];
            #pragma unroll
            for (int rr = 0; rr < 2; rr++) {
                int gm = gm0 + rr * 8;
                if (gm >= M) continue;
                #pragma unroll
                for (int cc = 0; cc < 2; cc++) {
                    int gn = gn0 + cc;
                    if (gn >= Nn) continue;
                    float vv = cr[rr * 2 + cc] * alpha;
                    if (bias) vv += bias[gn];
                    if (act == 1) vv = 0.5f * vv * (1.0f + erff(vv * 0.70710678118654752f));
                    if (res) vv += res[(long long)gm * ldc + gn];
                    C[(long long)gm * ldc + gn] = vv;
                }
            }
        }
    }
}

// ---------------- Split softmax, warp-per-row, single pass --------------------
__global__ void softmax_split(float* __restrict__ w) {
    long long row = (long long)blockIdx.x * 8 + (threadIdx.x >> 5);
    int lane = threadIdx.x & 31;
    float* p = w + row * SEQ;

    float v[19];
    #pragma unroll
    for (int j = 0; j < 19; j++) {
        int i = lane + j * 32;
        v[j] = (i < SEQ) ? p[i] : -1e30f;
    }
    bool in0 = lane < CLSK;

    float m0 = in0 ? v[0] : -1e30f;
    float m1 = in0 ? -1e30f : v[0];
    #pragma unroll
    for (int j = 1; j < 19; j++) m1 = fmaxf(m1, v[j]);
    #pragma unroll
    for (int o = 16; o; o >>= 1) {
        m0 = fmaxf(m0, __shfl_xor_sync(0xffffffffu, m0, o));
        m1 = fmaxf(m1, __shfl_xor_sync(0xffffffffu, m1, o));
    }

    float s0 = 0.f, s1 = 0.f;
    {
        float e = expf(v[0] - (in0 ? m0 : m1));
        v[0] = e;
        if (in0) s0 += e; else s1 += e;
    }
    #pragma unroll
    for (int j = 1; j < 19; j++) {
        int i = lane + j * 32;
        float e = (i < SEQ) ? expf(v[j] - m1) : 0.f;
        v[j] = e; s1 += e;
    }
    #pragma unroll
    for (int o = 16; o; o >>= 1) {
        s0 += __shfl_xor_sync(0xffffffffu, s0, o);
        s1 += __shfl_xor_sync(0xffffffffu, s1, o);
    }
    float r0 = 1.0f / s0, r1 = 1.0f / s1;

    p[lane] = v[0] * (in0 ? r0 : r1);
    #pragma unroll
    for (int j = 1; j < 19; j++) {
        int i = lane + j * 32;
        if (i < SEQ) p[i] = v[j] * r1;
    }
}

// ---------------- host-side orchestration -------------------------------------
extern "C" void kernel_launch(void* const* d_in, const int* in_sizes, int n_in,
                              void* d_out, int out_size) {
    const float* x      = (const float*)d_in[0];
    const float* qkv_w  = (const float*)d_in[1];
    const float* qkv_b  = (const float*)d_in[2];
    const float* proj_w = (const float*)d_in[3];
    const float* proj_b = (const float*)d_in[4];
    const float* ln1_g  = (const float*)d_in[5];
    const float* ln1_b  = (const float*)d_in[6];
    const float* ln2_g  = (const float*)d_in[7];
    const float* ln2_b  = (const float*)d_in[8];
    const float* fc1_w  = (const float*)d_in[9];
    const float* fc1_b  = (const float*)d_in[10];
    const float* fc2_w  = (const float*)d_in[11];
    const float* fc2_b  = (const float*)d_in[12];

    float* out_x = (float*)d_out;                                   // [16,596,768]
    float* out_w = out_x + (long long)ROWS * DIMC;                  // [16,12,596,596]

    float *h1, *qkv, *oc, *x2, *mlp;
    cudaGetSymbolAddress((void**)&h1,  g_h1);
    cudaGetSymbolAddress((void**)&qkv, g_qkv);
    cudaGetSymbolAddress((void**)&oc,  g_oc);
    cudaGetSymbolAddress((void**)&x2,  g_x2);
    cudaGetSymbolAddress((void**)&mlp, g_mlp);

    cudaFuncSetAttribute(gemm_tc, cudaFuncAttributeMaxDynamicSharedMemorySize, GEMM_SMEM);

    const long long sQb = (long long)SEQ * QKVC;
    const long long sWb = (long long)NHEADS * SEQ * SEQ;
    const long long sWh = (long long)SEQ * SEQ;
    const long long sOb = (long long)SEQ * DIMC;

    const int MB = (ROWS + BM - 1) / BM;   // 75
    const int SB = (SEQ + BM - 1) / BM;    // 5

    // 1. LN1
    ln_kernel<<<ROWS, 256>>>(x, ln1_g, ln1_b, h1);

    // 2. QKV projection
    gemm_tc<<<dim3(QKVC / BN, MB, 1), 256, GEMM_SMEM>>>(
        h1, qkv_w, qkv_b, nullptr, qkv,
        ROWS, QKVC, DIMC, DIMC, DIMC, QKVC,
        0, 0, 0, 0, 0, 0, 1.0f, 0, 0);

    // 3. S = (Q @ K^T) * scale -> weights output
    gemm_tc<<<dim3(SB, SB, BATCH * NHEADS), 256, GEMM_SMEM>>>(
        qkv, qkv + DIMC, nullptr, nullptr, out_w,
        SEQ, SEQ, HD, QKVC, QKVC, SEQ,
        sQb, HD, sQb, HD, sWb, sWh, 0.125f, 0, 0);

    // 4. split softmax in place
    softmax_split<<<(BATCH * NHEADS * SEQ) / 8, 256>>>(out_w);

    // 5. O = attn @ V
    gemm_tc<<<dim3(1, SB, BATCH * NHEADS), 256, GEMM_SMEM>>>(
        out_w, qkv + 2 * DIMC, nullptr, nullptr, oc,
        SEQ, HD, SEQ, SEQ, QKVC, DIMC,
        sWb, sWh, sQb, HD, sOb, HD, 1.0f, 0, 1);

    // 6. proj + residual
    gemm_tc<<<dim3(DIMC / BN, MB, 1), 256, GEMM_SMEM>>>(
        oc, proj_w, proj_b, x, x2,
        ROWS, DIMC, DIMC, DIMC, DIMC, DIMC,
        0, 0, 0, 0, 0, 0, 1.0f, 0, 0);

    // 7. LN2
    ln_kernel<<<ROWS, 256>>>(x2, ln2_g, ln2_b, h1);

    // 8. FC1 + exact GELU
    gemm_tc<<<dim3(HIDDEN / BN, MB, 1), 256, GEMM_SMEM>>>(
        h1, fc1_w, fc1_b, nullptr, mlp,
        ROWS, HIDDEN, DIMC, DIMC, DIMC, HIDDEN,
        0, 0, 0, 0, 0, 0, 1.0f, 1, 0);

    // 9. FC2 + residual -> final x output
    gemm_tc<<<dim3(DIMC / BN, MB, 1), 256, GEMM_SMEM>>>(
        mlp, fc2_w, fc2_b, x2, out_x,
        ROWS, DIMC, HIDDEN, HIDDEN, HIDDEN, DIMC,
        0, 0, 0, 0, 0, 0, 1.0f, 0, 0);
}

// round 5
// speedup vs baseline: 10.5772x; 1.9616x over previous
#include <cuda_runtime.h>
#include <cuda_fp16.h>
#include <math.h>
#include <stdint.h>

// Problem constants
#define DIMC   768
#define NHEADS 12
#define HD     64
#define BATCH  16
#define SEQ    596
#define SEQP   608              // SEQ padded to multiple of 32 (fp16 K-dim)
#define ROWS   (BATCH*SEQ)      // 9536
#define QKVC   2304
#define HIDDEN 3072
#define CLSK   20

// ---------------- scratch (static device globals; no allocation allowed) ----
__device__ __half g_h1h [ROWS*DIMC];            // LN output fp16
__device__ __half g_qkvh[ROWS*QKVC];            // qkv projection fp16
__device__ __half g_och [ROWS*DIMC];            // attention head-concat fp16
__device__ __half g_mlph[ROWS*HIDDEN];          // gelu(fc1) fp16
__device__ float  g_x2  [ROWS*DIMC];            // residual-1 fp32
__device__ __half g_atnh[BATCH*NHEADS*SEQ*SEQP];// softmax weights fp16, padded
__device__ __half g_vth [BATCH*NHEADS*HD*SEQP]; // V transposed fp16, padded
__device__ __half g_qkvwh[QKVC*DIMC];
__device__ __half g_projwh[DIMC*DIMC];
__device__ __half g_fc1wh[HIDDEN*DIMC];
__device__ __half g_fc2wh[DIMC*HIDDEN];

// ---------------- elementwise fp32 -> fp16 -------------------------------------
__global__ void f2h(const float* __restrict__ a, __half* __restrict__ o, int n) {
    int i = blockIdx.x * 256 + threadIdx.x;
    if (i < n) o[i] = __float2half_rn(a[i]);
}

// ---------------- LayerNorm: one block per row, fp16 out ----------------------
__global__ void ln_kernel(const float* __restrict__ x,
                          const float* __restrict__ g,
                          const float* __restrict__ b,
                          __half* __restrict__ out) {
    int row = blockIdx.x;
    const float* xr = x + (long long)row * DIMC;
    float s = 0.f, s2 = 0.f;
    for (int i = threadIdx.x; i < DIMC; i += blockDim.x) {
        float v = xr[i];
        s += v; s2 += v * v;
    }
    for (int o = 16; o; o >>= 1) {
        s  += __shfl_xor_sync(0xffffffffu, s,  o);
        s2 += __shfl_xor_sync(0xffffffffu, s2, o);
    }
    __shared__ float rs[8], rs2[8];
    int wid = threadIdx.x >> 5, lid = threadIdx.x & 31;
    if (lid == 0) { rs[wid] = s; rs2[wid] = s2; }
    __syncthreads();
    if (threadIdx.x == 0) {
        float a = 0.f, a2 = 0.f;
        for (int i = 0; i < (int)(blockDim.x >> 5); i++) { a += rs[i]; a2 += rs2[i]; }
        rs[0] = a; rs2[0] = a2;
    }
    __syncthreads();
    float mean = rs[0] * (1.0f / DIMC);
    float var  = rs2[0] * (1.0f / DIMC) - mean * mean;
    float inv  = rsqrtf(var + 1e-5f);
    __half* orow = out + (long long)row * DIMC;
    for (int i = threadIdx.x; i < DIMC; i += blockDim.x)
        orow[i] = __float2half_rn((xr[i] - mean) * inv * g[i] + b[i]);
}

// ---------------- V transpose: qkvh V slice -> vt [64, SEQP] fp16 --------------
__global__ void vtrans(const __half* __restrict__ qkvh, __half* __restrict__ vt) {
    int z = blockIdx.x;                 // b*12+h
    int b = z / NHEADS, h = z % NHEADS;
    __half* dst = vt + (long long)z * HD * SEQP;
    for (int i = threadIdx.x; i < HD * SEQP; i += blockDim.x) {
        int d = i / SEQP, s = i % SEQP;
        __half v = __float2half(0.f);
        if (s < SEQ)
            v = qkvh[((long long)(b * SEQ + s)) * QKVC + 2 * DIMC + h * HD + d];
        dst[(long long)d * SEQP + s] = v;
    }
}

// ---------------- fp16 tensor-core GEMM (TN), 4-stage cp.async -----------------
// C = act(alpha * A @ B^T + bias) [+ res];  A [M,K] fp16 lda, B [N,K] fp16 ldb.
// Outputs: Cf (fp32) and/or Ch (fp16), both ldc. Batched over gridDim.z.
#define BM 128
#define BN 128
#define BK 32
#define NSTG 4
#define SROWB 80                      // 32 halves padded to 40 (80 B) per row
#define TILE_B (128*SROWB)            // 10240 B
#define STG_B  (2*TILE_B)             // 20480 B
#define GEMM_SMEM (NSTG*STG_B)        // 81920 B

__device__ __forceinline__ void mma16(float* c, const uint32_t* a, const uint32_t* b) {
    asm volatile(
        "mma.sync.aligned.m16n8k16.row.col.f32.f16.f16.f32 "
        "{%0,%1,%2,%3}, {%4,%5,%6,%7}, {%8,%9}, {%0,%1,%2,%3};"
        : "+f"(c[0]), "+f"(c[1]), "+f"(c[2]), "+f"(c[3])
        : "r"(a[0]), "r"(a[1]), "r"(a[2]), "r"(a[3]), "r"(b[0]), "r"(b[1]));
}

__device__ __forceinline__ void cpa16(uint32_t dst, const void* src, bool pred) {
    unsigned ssz = pred ? 16u : 0u;
    asm volatile("cp.async.cg.shared.global [%0], [%1], 16, %2;"
                 :: "r"(dst), "l"(src), "r"(ssz));
}
__device__ __forceinline__ void cp_commit() { asm volatile("cp.async.commit_group;"); }

__global__ __launch_bounds__(256, 2)
void gemm_h(const __half* __restrict__ A, const __half* __restrict__ B,
            const float* __restrict__ bias, const float* __restrict__ res,
            float* __restrict__ Cf, __half* __restrict__ Ch,
            int M, int Nn, int K, int lda, int ldb, int ldc,
            long long sAb, long long sAh, long long sBb, long long sBh,
            long long sCb, long long sCh,
            float alpha, int act) {
    extern __shared__ __align__(16) char sh[];

    int z  = blockIdx.z;
    int zb = z / NHEADS, zh = z % NHEADS;
    A += zb * sAb + zh * sAh;
    B += zb * sBb + zh * sBh;
    long long coff = zb * sCb + zh * sCh;
    if (Cf) Cf += coff;
    if (Ch) Ch += coff;

    int tid = threadIdx.x, warp = tid >> 5, lane = tid & 31;
    int wm = warp >> 2, wn = warp & 3;
    int group = lane >> 2, tg = lane & 3;
    int row0 = blockIdx.y * BM, col0 = blockIdx.x * BN;

    float acc[4][4][4];
    #pragma unroll
    for (int i = 0; i < 4; i++)
        #pragma unroll
        for (int j = 0; j < 4; j++)
            #pragma unroll
            for (int r = 0; r < 4; r++) acc[i][j][r] = 0.f;

    auto load_tiles = [&](int s, int k0) {
        uint32_t a0 = (uint32_t)__cvta_generic_to_shared(sh + s * STG_B);
        uint32_t b0 = a0 + TILE_B;
        #pragma unroll
        for (int t = 0; t < 2; t++) {
            int i = tid + t * 256;
            int r = i >> 2, c = i & 3;          // row, 8-half chunk
            int gr = row0 + r;
            bool p = gr < M;
            cpa16(a0 + r * SROWB + c * 16,
                  A + (long long)gr * lda + k0 + c * 8, p);
        }
        #pragma unroll
        for (int t = 0; t < 2; t++) {
            int i = tid + t * 256;
            int r = i >> 2, c = i & 3;
            int gn = col0 + r;
            bool p = gn < Nn;
            cpa16(b0 + r * SROWB + c * 16,
                  B + (long long)gn * ldb + k0 + c * 8, p);
        }
    };

    auto compute = [&](int s) {
        const uint32_t* Aw = (const uint32_t*)(sh + s * STG_B);
        const uint32_t* Bw = (const uint32_t*)(sh + s * STG_B + TILE_B);
        #pragma unroll
        for (int ks = 0; ks < 2; ks++) {
            int kw = ks * 8 + tg;
            uint32_t a[4][4], b[4][2];
            #pragma unroll
            for (int mt = 0; mt < 4; mt++) {
                int m = wm * 64 + mt * 16 + group;
                a[mt][0] = Aw[m * 20 + kw];
                a[mt][1] = Aw[(m + 8) * 20 + kw];
                a[mt][2] = Aw[m * 20 + kw + 4];
                a[mt][3] = Aw[(m + 8) * 20 + kw + 4];
            }
            #pragma unroll
            for (int nt = 0; nt < 4; nt++) {
                int n = wn * 32 + nt * 8 + group;
                b[nt][0] = Bw[n * 20 + kw];
                b[nt][1] = Bw[n * 20 + kw + 4];
            }
            #pragma unroll
            for (int mt = 0; mt < 4; mt++)
                #pragma unroll
                for (int nt = 0; nt < 4; nt++)
                    mma16(acc[mt][nt], a[mt], b[nt]);
        }
    };

    int nT = K / BK;

    #pragma unroll
    for (int s = 0; s < NSTG - 1; s++) {
        if (s < nT) load_tiles(s, s * BK);
        cp_commit();
    }

    for (int t = 0; t < nT; t++) {
        asm volatile("cp.async.wait_group %0;" :: "n"(NSTG - 2));
        __syncthreads();
        compute(t % NSTG);
        int pf = t + NSTG - 1;
        if (pf < nT) load_tiles(pf % NSTG, pf * BK);
        cp_commit();
    }

    // ---- epilogue: each acc reg-pair is a float2 at (gr|gr+8, gc) ----
    #pragma unroll
    for (int mt = 0; mt < 4; mt++) {
        #pragma unroll
        for (int nt = 0; nt < 4; nt++) {
            int gc = col0 + wn * 32 + nt * 8 + tg * 2;
            if (gc >= Nn) continue;
            float bx = 0.f, by = 0.f;
            if (bias) { bx = bias[gc]; by = bias[gc + 1]; }
            #pragma unroll
            for (int half_ = 0; half_ < 2; half_++) {
                int gm = row0 + wm * 64 + mt * 16 + group + half_ * 8;
                if (gm >= M) continue;
                float v0 = acc[mt][nt][half_ * 2]     * alpha + bx;
                float v1 = acc[mt][nt][half_ * 2 + 1] * alpha + by;
                if (act == 1) {
                    v0 = 0.5f * v0 * (1.0f + erff(v0 * 0.70710678118654752f));
                    v1 = 0.5f * v1 * (1.0f + erff(v1 * 0.70710678118654752f));
                }
                if (res) {
                    float2 rr = *(const float2*)(res + (long long)gm * ldc + gc);
                    v0 += rr.x; v1 += rr.y;
                }
                if (Cf) *(float2*)(Cf + (long long)gm * ldc + gc) = make_float2(v0, v1);
                if (Ch) *(__half2*)(Ch + (long long)gm * ldc + gc) =
                            __floats2half2_rn(v0, v1);
            }
        }
    }
}

// ---------------- Split softmax, warp-per-row; fp32 in-place + fp16 copy -------
__global__ void softmax_split(float* __restrict__ w, __half* __restrict__ wh) {
    long long row = (long long)blockIdx.x * 8 + (threadIdx.x >> 5);
    int lane = threadIdx.x & 31;
    float* p = w + row * SEQ;
    __half* ph = wh + row * SEQP;

    float v[19];
    #pragma unroll
    for (int j = 0; j < 19; j++) {
        int i = lane + j * 32;
        v[j] = (i < SEQ) ? p[i] : -1e30f;
    }
    bool in0 = lane < CLSK;

    float m0 = in0 ? v[0] : -1e30f;
    float m1 = in0 ? -1e30f : v[0];
    #pragma unroll
    for (int j = 1; j < 19; j++) m1 = fmaxf(m1, v[j]);
    #pragma unroll
    for (int o = 16; o; o >>= 1) {
        m0 = fmaxf(m0, __shfl_xor_sync(0xffffffffu, m0, o));
        m1 = fmaxf(m1, __shfl_xor_sync(0xffffffffu, m1, o));
    }

    float s0 = 0.f, s1 = 0.f;
    {
        float e = expf(v[0] - (in0 ? m0 : m1));
        v[0] = e;
        if (in0) s0 += e; else s1 += e;
    }
    #pragma unroll
    for (int j = 1; j < 19; j++) {
        int i = lane + j * 32;
        float e = (i < SEQ) ? expf(v[j] - m1) : 0.f;
        v[j] = e; s1 += e;
    }
    #pragma unroll
    for (int o = 16; o; o >>= 1) {
        s0 += __shfl_xor_sync(0xffffffffu, s0, o);
        s1 += __shfl_xor_sync(0xffffffffu, s1, o);
    }
    float r0 = 1.0f / s0, r1 = 1.0f / s1;

    {
        float out = v[0] * (in0 ? r0 : r1);
        p[lane] = out;
        ph[lane] = __float2half_rn(out);
    }
    #pragma unroll
    for (int j = 1; j < 19; j++) {
        int i = lane + j * 32;
        if (i < SEQ) {
            float out = v[j] * r1;
            p[i] = out;
            ph[i] = __float2half_rn(out);
        }
    }
    if (lane < SEQP - SEQ) ph[SEQ + lane] = __float2half(0.f);
}

// ---------------- host-side orchestration -------------------------------------
extern "C" void kernel_launch(void* const* d_in, const int* in_sizes, int n_in,
                              void* d_out, int out_size) {
    const float* x      = (const float*)d_in[0];
    const float* qkv_w  = (const float*)d_in[1];
    const float* qkv_b  = (const float*)d_in[2];
    const float* proj_w = (const float*)d_in[3];
    const float* proj_b = (const float*)d_in[4];
    const float* ln1_g  = (const float*)d_in[5];
    const float* ln1_b  = (const float*)d_in[6];
    const float* ln2_g  = (const float*)d_in[7];
    const float* ln2_b  = (const float*)d_in[8];
    const float* fc1_w  = (const float*)d_in[9];
    const float* fc1_b  = (const float*)d_in[10];
    const float* fc2_w  = (const float*)d_in[11];
    const float* fc2_b  = (const float*)d_in[12];

    float* out_x = (float*)d_out;                                   // [16,596,768]
    float* out_w = out_x + (long long)ROWS * DIMC;                  // [16,12,596,596]

    __half *h1h, *qkvh, *och, *mlph, *atnh, *vth, *qkvwh, *projwh, *fc1wh, *fc2wh;
    float* x2;
    cudaGetSymbolAddress((void**)&h1h,   g_h1h);
    cudaGetSymbolAddress((void**)&qkvh,  g_qkvh);
    cudaGetSymbolAddress((void**)&och,   g_och);
    cudaGetSymbolAddress((void**)&mlph,  g_mlph);
    cudaGetSymbolAddress((void**)&x2,    g_x2);
    cudaGetSymbolAddress((void**)&atnh,  g_atnh);
    cudaGetSymbolAddress((void**)&vth,   g_vth);
    cudaGetSymbolAddress((void**)&qkvwh, g_qkvwh);
    cudaGetSymbolAddress((void**)&projwh,g_projwh);
    cudaGetSymbolAddress((void**)&fc1wh, g_fc1wh);
    cudaGetSymbolAddress((void**)&fc2wh, g_fc2wh);

    cudaFuncSetAttribute(gemm_h, cudaFuncAttributeMaxDynamicSharedMemorySize, GEMM_SMEM);

    // weight conversions (independent of LN)
    f2h<<<(QKVC * DIMC + 255) / 256, 256>>>(qkv_w, qkvwh, QKVC * DIMC);
    f2h<<<(DIMC * DIMC + 255) / 256, 256>>>(proj_w, projwh, DIMC * DIMC);
    f2h<<<(HIDDEN * DIMC + 255) / 256, 256>>>(fc1_w, fc1wh, HIDDEN * DIMC);
    f2h<<<(DIMC * HIDDEN + 255) / 256, 256>>>(fc2_w, fc2wh, DIMC * HIDDEN);

    const long long sQb = (long long)SEQ * QKVC;                // qkvh per-batch
    const long long sWb = (long long)NHEADS * SEQ * SEQ;        // out_w per-batch
    const long long sWh = (long long)SEQ * SEQ;
    const long long sAtb = (long long)NHEADS * SEQ * SEQP;      // atnh
    const long long sAth = (long long)SEQ * SEQP;
    const long long sVtb = (long long)NHEADS * HD * SEQP;       // vth
    const long long sVth = (long long)HD * SEQP;
    const long long sOb = (long long)SEQ * DIMC;

    const int MB = (ROWS + BM - 1) / BM;   // 75
    const int SB = (SEQ + BM - 1) / BM;    // 5

    // 1. LN1 -> fp16
    ln_kernel<<<ROWS, 256>>>(x, ln1_g, ln1_b, h1h);

    // 2. QKV projection -> fp16
    gemm_h<<<dim3(QKVC / BN, MB, 1), 256, GEMM_SMEM>>>(
        h1h, qkvwh, qkv_b, nullptr, nullptr, qkvh,
        ROWS, QKVC, DIMC, DIMC, DIMC, QKVC,
        0, 0, 0, 0, 0, 0, 1.0f, 0);

    // 2b. transpose V per (b,h) -> vt [64, SEQP]
    vtrans<<<BATCH * NHEADS, 256>>>(qkvh, vth);

    // 3. S = (Q @ K^T) * scale -> weights output fp32
    gemm_h<<<dim3(SB, SB, BATCH * NHEADS), 256, GEMM_SMEM>>>(
        qkvh, qkvh + DIMC, nullptr, nullptr, out_w, nullptr,
        SEQ, SEQ, HD, QKVC, QKVC, SEQ,
        sQb, HD, sQb, HD, sWb, sWh, 0.125f, 0);

    // 4. split softmax: fp32 in place + fp16 padded copy
    softmax_split<<<(BATCH * NHEADS * SEQ) / 8, 256>>>(out_w, atnh);

    // 5. O = attn @ V  (TN: B = V^T [64, SEQP]) -> fp16 head-concat
    gemm_h<<<dim3(1, SB, BATCH * NHEADS), 256, GEMM_SMEM>>>(
        atnh, vth, nullptr, nullptr, nullptr, och,
        SEQ, HD, SEQP, SEQP, SEQP, DIMC,
        sAtb, sAth, sVtb, sVth, sOb, HD, 1.0f, 0);

    // 6. proj + residual -> x2 fp32
    gemm_h<<<dim3(DIMC / BN, MB, 1), 256, GEMM_SMEM>>>(
        och, projwh, proj_b, x, x2, nullptr,
        ROWS, DIMC, DIMC, DIMC, DIMC, DIMC,
        0, 0, 0, 0, 0, 0, 1.0f, 0);

    // 7. LN2 -> fp16
    ln_kernel<<<ROWS, 256>>>(x2, ln2_g, ln2_b, h1h);

    // 8. FC1 + exact GELU -> fp16
    gemm_h<<<dim3(HIDDEN / BN, MB, 1), 256, GEMM_SMEM>>>(
        h1h, fc1wh, fc1_b, nullptr, nullptr, mlph,
        ROWS, HIDDEN, DIMC, DIMC, DIMC, HIDDEN,
        0, 0, 0, 0, 0, 0, 1.0f, 1);

    // 9. FC2 + residual -> final x output fp32
    gemm_h<<<dim3(DIMC / BN, MB, 1), 256, GEMM_SMEM>>>(
        mlph, fc2wh, fc2_b, x2, out_x, nullptr,
        ROWS, DIMC, HIDDEN, HIDDEN, HIDDEN, DIMC,
        0, 0, 0, 0, 0, 0, 1.0f, 0);
}

// round 6
// speedup vs baseline: 11.1163x; 1.0510x over previous
#include <cuda_runtime.h>
#include <cuda_fp16.h>
#include <math.h>
#include <stdint.h>

// Problem constants
#define DIMC   768
#define NHEADS 12
#define HD     64
#define BATCH  16
#define SEQ    596
#define SEQP   640              // SEQ padded to multiple of 64
#define ROWS   (BATCH*SEQ)      // 9536
#define QKVC   2304
#define HIDDEN 3072
#define CLSK   20

// ---------------- scratch (static device globals) ------------------------------
__device__ __half g_h1h [ROWS*DIMC];
__device__ __half g_qkvh[ROWS*QKVC];
__device__ __half g_och [ROWS*DIMC];
__device__ __half g_mlph[ROWS*HIDDEN];
__device__ float  g_x2  [ROWS*DIMC];
__device__ __half g_atnh[(long long)BATCH*NHEADS*SEQ*SEQP];
__device__ __half g_vth [(long long)BATCH*NHEADS*HD*SEQP];
__device__ __half g_qkvwh[QKVC*DIMC];
__device__ __half g_projwh[DIMC*DIMC];
__device__ __half g_fc1wh[HIDDEN*DIMC];
__device__ __half g_fc2wh[DIMC*HIDDEN];

// ---------------- elementwise fp32 -> fp16 -------------------------------------
__global__ void f2h(const float* __restrict__ a, __half* __restrict__ o, int n) {
    int i = blockIdx.x * 256 + threadIdx.x;
    if (i < n) o[i] = __float2half_rn(a[i]);
}

// ---------------- LayerNorm -----------------------------------------------------
__global__ void ln_kernel(const float* __restrict__ x,
                          const float* __restrict__ g,
                          const float* __restrict__ b,
                          __half* __restrict__ out) {
    int row = blockIdx.x;
    const float* xr = x + (long long)row * DIMC;
    float s = 0.f, s2 = 0.f;
    for (int i = threadIdx.x; i < DIMC; i += blockDim.x) {
        float v = xr[i];
        s += v; s2 += v * v;
    }
    for (int o = 16; o; o >>= 1) {
        s  += __shfl_xor_sync(0xffffffffu, s,  o);
        s2 += __shfl_xor_sync(0xffffffffu, s2, o);
    }
    __shared__ float rs[8], rs2[8];
    int wid = threadIdx.x >> 5, lid = threadIdx.x & 31;
    if (lid == 0) { rs[wid] = s; rs2[wid] = s2; }
    __syncthreads();
    if (threadIdx.x == 0) {
        float a = 0.f, a2 = 0.f;
        for (int i = 0; i < (int)(blockDim.x >> 5); i++) { a += rs[i]; a2 += rs2[i]; }
        rs[0] = a; rs2[0] = a2;
    }
    __syncthreads();
    float mean = rs[0] * (1.0f / DIMC);
    float var  = rs2[0] * (1.0f / DIMC) - mean * mean;
    float inv  = rsqrtf(var + 1e-5f);
    __half* orow = out + (long long)row * DIMC;
    for (int i = threadIdx.x; i < DIMC; i += blockDim.x)
        orow[i] = __float2half_rn((xr[i] - mean) * inv * g[i] + b[i]);
}

// ---------------- V transpose: qkvh V slice -> vt [64, SEQP] --------------------
__global__ void vtrans(const __half* __restrict__ qkvh, __half* __restrict__ vt) {
    int z = blockIdx.x;
    int b = z / NHEADS, h = z % NHEADS;
    __half* dst = vt + (long long)z * HD * SEQP;
    for (int i = threadIdx.x; i < HD * SEQP; i += blockDim.x) {
        int d = i / SEQP, s = i % SEQP;
        __half v = __float2half(0.f);
        if (s < SEQ)
            v = qkvh[((long long)(b * SEQ + s)) * QKVC + 2 * DIMC + h * HD + d];
        dst[(long long)d * SEQP + s] = v;
    }
}

// ---------------- fp16 tensor-core GEMM (TN), ldmatrix + 3-stage cp.async -------
// C = act(alpha * A @ B^T + bias) [+ res];  A [M,K] fp16, B [N,K] fp16.
// BM=128, BK=64. Template: BN_, WNS (warp cols), MT (16-row tiles/warp),
// NT (8-col tiles/warp).  8 warps: wm = warp/WNS, wn = warp%WNS.
#define BK 64
#define SROWB 144     // 64 halves (128B) + 16B pad; stride 36 words -> no conflicts
#define NSTG 3

__device__ __forceinline__ void mma16(float* c, const uint32_t* a, const uint32_t* b) {
    asm volatile(
        "mma.sync.aligned.m16n8k16.row.col.f32.f16.f16.f32 "
        "{%0,%1,%2,%3}, {%4,%5,%6,%7}, {%8,%9}, {%0,%1,%2,%3};"
        : "+f"(c[0]), "+f"(c[1]), "+f"(c[2]), "+f"(c[3])
        : "r"(a[0]), "r"(a[1]), "r"(a[2]), "r"(a[3]), "r"(b[0]), "r"(b[1]));
}
__device__ __forceinline__ void cpa16(uint32_t dst, const void* src, bool pred) {
    unsigned ssz = pred ? 16u : 0u;
    asm volatile("cp.async.cg.shared.global [%0], [%1], 16, %2;"
                 :: "r"(dst), "l"(src), "r"(ssz));
}
__device__ __forceinline__ void cp_commit() { asm volatile("cp.async.commit_group;"); }

__device__ __forceinline__ void ldmA(uint32_t* a, uint32_t base, int m0, int kb, int lane) {
    uint32_t addr = base + (uint32_t)(m0 + (lane & 15)) * SROWB
                  + (uint32_t)(kb + (lane >> 4) * 8) * 2;
    asm volatile("ldmatrix.sync.aligned.m8n8.x4.shared.b16 {%0,%1,%2,%3}, [%4];"
                 : "=r"(a[0]), "=r"(a[1]), "=r"(a[2]), "=r"(a[3]) : "r"(addr));
}
// loads B fragments for two adjacent 8-col n-tiles: out[0..1]=nt, out[2..3]=nt+1
__device__ __forceinline__ void ldmB2(uint32_t* b, uint32_t base, int n0, int kb, int lane) {
    uint32_t addr = base + (uint32_t)(n0 + (lane & 7) + ((lane >> 4) * 8)) * SROWB
                  + (uint32_t)(kb + ((lane >> 3) & 1) * 8) * 2;
    asm volatile("ldmatrix.sync.aligned.m8n8.x4.shared.b16 {%0,%1,%2,%3}, [%4];"
                 : "=r"(b[0]), "=r"(b[1]), "=r"(b[2]), "=r"(b[3]) : "r"(addr));
}

template<int BN_, int WNS, int MT, int NT>
__global__ __launch_bounds__(256, 2)
void gemm_h(const __half* __restrict__ A, const __half* __restrict__ B,
            const float* __restrict__ bias, const float* __restrict__ res,
            float* __restrict__ Cf, __half* __restrict__ Ch,
            int M, int Nn, int K, int lda, int ldb, int ldc,
            long long sAb, long long sAh, long long sBb, long long sBh,
            long long sCb, long long sCh,
            float alpha, int act) {
    constexpr int TILE_A = 128 * SROWB;
    constexpr int TILE_Bt = BN_ * SROWB;
    constexpr int STG = TILE_A + TILE_Bt;
    extern __shared__ __align__(16) char sh[];
    uint32_t shb = (uint32_t)__cvta_generic_to_shared(sh);

    int z  = blockIdx.z;
    int zb = z / NHEADS, zh = z % NHEADS;
    A += zb * sAb + zh * sAh;
    B += zb * sBb + zh * sBh;
    long long coff = zb * sCb + zh * sCh;
    if (Cf) Cf += coff;
    if (Ch) Ch += coff;

    int tid = threadIdx.x, warp = tid >> 5, lane = tid & 31;
    int wm = warp / WNS, wn = warp % WNS;
    int group = lane >> 2, tg = lane & 3;
    int row0 = blockIdx.y * 128, col0 = blockIdx.x * BN_;

    float acc[MT][NT][4];
    #pragma unroll
    for (int i = 0; i < MT; i++)
        #pragma unroll
        for (int j = 0; j < NT; j++)
            #pragma unroll
            for (int r = 0; r < 4; r++) acc[i][j][r] = 0.f;

    auto load_tiles = [&](int s, int k0) {
        uint32_t a0 = shb + s * STG;
        uint32_t b0 = a0 + TILE_A;
        #pragma unroll
        for (int t = 0; t < 4; t++) {
            int i = tid + t * 256;
            int r = i >> 3, c = i & 7;
            int gr = row0 + r;
            cpa16(a0 + r * SROWB + c * 16, A + (long long)gr * lda + k0 + c * 8, gr < M);
        }
        #pragma unroll
        for (int t = 0; t < BN_ / 32; t++) {
            int i = tid + t * 256;
            int r = i >> 3, c = i & 7;
            int gn = col0 + r;
            cpa16(b0 + r * SROWB + c * 16, B + (long long)gn * ldb + k0 + c * 8, gn < Nn);
        }
    };

    auto compute = [&](int s) {
        uint32_t a0 = shb + s * STG;
        uint32_t b0 = a0 + TILE_A;
        #pragma unroll
        for (int ks = 0; ks < 4; ks++) {
            int kb = ks * 16;
            uint32_t a[MT][4], b[NT][2];
            #pragma unroll
            for (int mt = 0; mt < MT; mt++)
                ldmA(a[mt], a0, wm * MT * 16 + mt * 16, kb, lane);
            #pragma unroll
            for (int nt = 0; nt < NT; nt += 2) {
                uint32_t bb[4];
                ldmB2(bb, b0, wn * NT * 8 + nt * 8, kb, lane);
                b[nt][0] = bb[0]; b[nt][1] = bb[1];
                b[nt + 1][0] = bb[2]; b[nt + 1][1] = bb[3];
            }
            #pragma unroll
            for (int mt = 0; mt < MT; mt++)
                #pragma unroll
                for (int nt = 0; nt < NT; nt++)
                    mma16(acc[mt][nt], a[mt], b[nt]);
        }
    };

    int nT = K / BK;

    #pragma unroll
    for (int s = 0; s < NSTG - 1; s++) {
        if (s < nT) load_tiles(s, s * BK);
        cp_commit();
    }

    for (int t = 0; t < nT; t++) {
        asm volatile("cp.async.wait_group %0;" :: "n"(NSTG - 2));
        __syncthreads();
        int pf = t + NSTG - 1;
        if (pf < nT) load_tiles(pf % NSTG, pf * BK);
        cp_commit();
        compute(t % NSTG);
    }

    // ---- epilogue ----
    #pragma unroll
    for (int mt = 0; mt < MT; mt++) {
        #pragma unroll
        for (int nt = 0; nt < NT; nt++) {
            int gc = col0 + wn * NT * 8 + nt * 8 + tg * 2;
            if (gc >= Nn) continue;
            float bx = 0.f, by = 0.f;
            if (bias) { bx = bias[gc]; by = bias[gc + 1]; }
            #pragma unroll
            for (int hf = 0; hf < 2; hf++) {
                int gm = row0 + wm * MT * 16 + mt * 16 + group + hf * 8;
                if (gm >= M) continue;
                float v0 = acc[mt][nt][hf * 2]     * alpha + bx;
                float v1 = acc[mt][nt][hf * 2 + 1] * alpha + by;
                if (act == 1) {
                    v0 = 0.5f * v0 * (1.0f + erff(v0 * 0.70710678118654752f));
                    v1 = 0.5f * v1 * (1.0f + erff(v1 * 0.70710678118654752f));
                }
                if (res) {
                    float2 rr = *(const float2*)(res + (long long)gm * ldc + gc);
                    v0 += rr.x; v1 += rr.y;
                }
                if (Cf) *(float2*)(Cf + (long long)gm * ldc + gc) = make_float2(v0, v1);
                if (Ch) *(__half2*)(Ch + (long long)gm * ldc + gc) =
                            __floats2half2_rn(v0, v1);
            }
        }
    }
}

// ---------------- Split softmax, warp-per-row; fp32 in-place + fp16 copy --------
__global__ void softmax_split(float* __restrict__ w, __half* __restrict__ wh) {
    long long row = (long long)blockIdx.x * 8 + (threadIdx.x >> 5);
    int lane = threadIdx.x & 31;
    float* p = w + row * SEQ;
    __half* ph = wh + row * SEQP;

    float v[19];
    #pragma unroll
    for (int j = 0; j < 19; j++) {
        int i = lane + j * 32;
        v[j] = (i < SEQ) ? p[i] : -1e30f;
    }
    bool in0 = lane < CLSK;

    float m0 = in0 ? v[0] : -1e30f;
    float m1 = in0 ? -1e30f : v[0];
    #pragma unroll
    for (int j = 1; j < 19; j++) m1 = fmaxf(m1, v[j]);
    #pragma unroll
    for (int o = 16; o; o >>= 1) {
        m0 = fmaxf(m0, __shfl_xor_sync(0xffffffffu, m0, o));
        m1 = fmaxf(m1, __shfl_xor_sync(0xffffffffu, m1, o));
    }

    float s0 = 0.f, s1 = 0.f;
    {
        float e = expf(v[0] - (in0 ? m0 : m1));
        v[0] = e;
        if (in0) s0 += e; else s1 += e;
    }
    #pragma unroll
    for (int j = 1; j < 19; j++) {
        int i = lane + j * 32;
        float e = (i < SEQ) ? expf(v[j] - m1) : 0.f;
        v[j] = e; s1 += e;
    }
    #pragma unroll
    for (int o = 16; o; o >>= 1) {
        s0 += __shfl_xor_sync(0xffffffffu, s0, o);
        s1 += __shfl_xor_sync(0xffffffffu, s1, o);
    }
    float r0 = 1.0f / s0, r1 = 1.0f / s1;

    {
        float out = v[0] * (in0 ? r0 : r1);
        p[lane] = out;
        ph[lane] = __float2half_rn(out);
    }
    #pragma unroll
    for (int j = 1; j < 19; j++) {
        int i = lane + j * 32;
        if (i < SEQ) {
            float out = v[j] * r1;
            p[i] = out;
            ph[i] = __float2half_rn(out);
        }
    }
    for (int i = SEQ + lane; i < SEQP; i += 32) ph[i] = __float2half(0.f);
}

// ---------------- host-side orchestration ---------------------------------------
extern "C" void kernel_launch(void* const* d_in, const int* in_sizes, int n_in,
                              void* d_out, int out_size) {
    const float* x      = (const float*)d_in[0];
    const float* qkv_w  = (const float*)d_in[1];
    const float* qkv_b  = (const float*)d_in[2];
    const float* proj_w = (const float*)d_in[3];
    const float* proj_b = (const float*)d_in[4];
    const float* ln1_g  = (const float*)d_in[5];
    const float* ln1_b  = (const float*)d_in[6];
    const float* ln2_g  = (const float*)d_in[7];
    const float* ln2_b  = (const float*)d_in[8];
    const float* fc1_w  = (const float*)d_in[9];
    const float* fc1_b  = (const float*)d_in[10];
    const float* fc2_w  = (const float*)d_in[11];
    const float* fc2_b  = (const float*)d_in[12];

    float* out_x = (float*)d_out;
    float* out_w = out_x + (long long)ROWS * DIMC;

    __half *h1h, *qkvh, *och, *mlph, *atnh, *vth, *qkvwh, *projwh, *fc1wh, *fc2wh;
    float* x2;
    cudaGetSymbolAddress((void**)&h1h,   g_h1h);
    cudaGetSymbolAddress((void**)&qkvh,  g_qkvh);
    cudaGetSymbolAddress((void**)&och,   g_och);
    cudaGetSymbolAddress((void**)&mlph,  g_mlph);
    cudaGetSymbolAddress((void**)&x2,    g_x2);
    cudaGetSymbolAddress((void**)&atnh,  g_atnh);
    cudaGetSymbolAddress((void**)&vth,   g_vth);
    cudaGetSymbolAddress((void**)&qkvwh, g_qkvwh);
    cudaGetSymbolAddress((void**)&projwh,g_projwh);
    cudaGetSymbolAddress((void**)&fc1wh, g_fc1wh);
    cudaGetSymbolAddress((void**)&fc2wh, g_fc2wh);

    const int SM128 = NSTG * (128 + 128) * SROWB;   // 110592 B
    const int SM64  = NSTG * (128 + 64)  * SROWB;   //  82944 B
    cudaFuncSetAttribute((const void*)gemm_h<128,4,4,4>,
                         cudaFuncAttributeMaxDynamicSharedMemorySize, SM128);
    cudaFuncSetAttribute((const void*)gemm_h<64,2,2,4>,
                         cudaFuncAttributeMaxDynamicSharedMemorySize, SM64);

    f2h<<<(QKVC * DIMC + 255) / 256, 256>>>(qkv_w, qkvwh, QKVC * DIMC);
    f2h<<<(DIMC * DIMC + 255) / 256, 256>>>(proj_w, projwh, DIMC * DIMC);
    f2h<<<(HIDDEN * DIMC + 255) / 256, 256>>>(fc1_w, fc1wh, HIDDEN * DIMC);
    f2h<<<(DIMC * HIDDEN + 255) / 256, 256>>>(fc2_w, fc2wh, DIMC * HIDDEN);

    const long long sQb  = (long long)SEQ * QKVC;
    const long long sWb  = (long long)NHEADS * SEQ * SEQ;
    const long long sWh  = (long long)SEQ * SEQ;
    const long long sAtb = (long long)NHEADS * SEQ * SEQP;
    const long long sAth = (long long)SEQ * SEQP;
    const long long sVtb = (long long)NHEADS * HD * SEQP;
    const long long sVth = (long long)HD * SEQP;
    const long long sOb  = (long long)SEQ * DIMC;

    const int MB = (ROWS + 127) / 128;   // 75
    const int SB = (SEQ + 127) / 128;    // 5

    // 1. LN1 -> fp16
    ln_kernel<<<ROWS, 256>>>(x, ln1_g, ln1_b, h1h);

    // 2. QKV projection -> fp16
    gemm_h<128,4,4,4><<<dim3(QKVC / 128, MB, 1), 256, SM128>>>(
        h1h, qkvwh, qkv_b, nullptr, nullptr, qkvh,
        ROWS, QKVC, DIMC, DIMC, DIMC, QKVC,
        0, 0, 0, 0, 0, 0, 1.0f, 0);

    // 2b. V transpose per (b,h)
    vtrans<<<BATCH * NHEADS, 256>>>(qkvh, vth);

    // 3. S = (Q @ K^T) * scale -> weights output fp32
    gemm_h<128,4,4,4><<<dim3(SB, SB, BATCH * NHEADS), 256, SM128>>>(
        qkvh, qkvh + DIMC, nullptr, nullptr, out_w, nullptr,
        SEQ, SEQ, HD, QKVC, QKVC, SEQ,
        sQb, HD, sQb, HD, sWb, sWh, 0.125f, 0);

    // 4. split softmax: fp32 in place + fp16 padded copy
    softmax_split<<<(BATCH * NHEADS * SEQ) / 8, 256>>>(out_w, atnh);

    // 5. O = attn @ V  (BN=64 tile) -> fp16 head-concat
    gemm_h<64,2,2,4><<<dim3(1, SB, BATCH * NHEADS), 256, SM64>>>(
        atnh, vth, nullptr, nullptr, nullptr, och,
        SEQ, HD, SEQP, SEQP, SEQP, DIMC,
        sAtb, sAth, sVtb, sVth, sOb, HD, 1.0f, 0);

    // 6. proj + residual -> x2 fp32
    gemm_h<128,4,4,4><<<dim3(DIMC / 128, MB, 1), 256, SM128>>>(
        och, projwh, proj_b, x, x2, nullptr,
        ROWS, DIMC, DIMC, DIMC, DIMC, DIMC,
        0, 0, 0, 0, 0, 0, 1.0f, 0);

    // 7. LN2 -> fp16
    ln_kernel<<<ROWS, 256>>>(x2, ln2_g, ln2_b, h1h);

    // 8. FC1 + exact GELU -> fp16
    gemm_h<128,4,4,4><<<dim3(HIDDEN / 128, MB, 1), 256, SM128>>>(
        h1h, fc1wh, fc1_b, nullptr, nullptr, mlph,
        ROWS, HIDDEN, DIMC, DIMC, DIMC, HIDDEN,
        0, 0, 0, 0, 0, 0, 1.0f, 1);

    // 9. FC2 + residual -> final x output fp32
    gemm_h<128,4,4,4><<<dim3(DIMC / 128, MB, 1), 256, SM128>>>(
        mlph, fc2wh, fc2_b, x2, out_x, nullptr,
        ROWS, DIMC, HIDDEN, HIDDEN, HIDDEN, DIMC,
        0, 0, 0, 0, 0, 0, 1.0f, 0);
}

// round 7
// speedup vs baseline: 12.2333x; 1.1005x over previous
#include <cuda_runtime.h>
#include <cuda_fp16.h>
#include <math.h>
#include <stdint.h>

// Problem constants
#define DIMC   768
#define NHEADS 12
#define HD     64
#define BATCH  16
#define SEQ    596
#define SEQP   640
#define ROWS   (BATCH*SEQ)      // 9536
#define QKVC   2304
#define HIDDEN 3072
#define CLSK   20

// ---------------- scratch ---------------------------------------------------------
__device__ __half g_h1h [ROWS*DIMC];
__device__ __half g_qkvh[ROWS*QKVC];
__device__ __half g_och [ROWS*DIMC];
__device__ __half g_mlph[ROWS*HIDDEN];
__device__ float  g_x2  [ROWS*DIMC];
__device__ __half g_qkvwh[QKVC*DIMC];
__device__ __half g_projwh[DIMC*DIMC];
__device__ __half g_fc1wh[HIDDEN*DIMC];
__device__ __half g_fc2wh[DIMC*HIDDEN];

// ---------------- fp32 -> fp16, vectorized ----------------------------------------
__global__ void f2h4(const float4* __restrict__ a, __half2* __restrict__ o, int n4) {
    int i = blockIdx.x * 256 + threadIdx.x;
    if (i < n4) {
        float4 v = a[i];
        o[2 * i]     = __floats2half2_rn(v.x, v.y);
        o[2 * i + 1] = __floats2half2_rn(v.z, v.w);
    }
}

// ---------------- LayerNorm --------------------------------------------------------
__global__ void ln_kernel(const float* __restrict__ x,
                          const float* __restrict__ g,
                          const float* __restrict__ b,
                          __half* __restrict__ out) {
    int row = blockIdx.x;
    const float* xr = x + (long long)row * DIMC;
    float s = 0.f, s2 = 0.f;
    for (int i = threadIdx.x; i < DIMC; i += blockDim.x) {
        float v = xr[i];
        s += v; s2 += v * v;
    }
    for (int o = 16; o; o >>= 1) {
        s  += __shfl_xor_sync(0xffffffffu, s,  o);
        s2 += __shfl_xor_sync(0xffffffffu, s2, o);
    }
    __shared__ float rs[8], rs2[8];
    int wid = threadIdx.x >> 5, lid = threadIdx.x & 31;
    if (lid == 0) { rs[wid] = s; rs2[wid] = s2; }
    __syncthreads();
    if (threadIdx.x == 0) {
        float a = 0.f, a2 = 0.f;
        for (int i = 0; i < (int)(blockDim.x >> 5); i++) { a += rs[i]; a2 += rs2[i]; }
        rs[0] = a; rs2[0] = a2;
    }
    __syncthreads();
    float mean = rs[0] * (1.0f / DIMC);
    float var  = rs2[0] * (1.0f / DIMC) - mean * mean;
    float inv  = rsqrtf(var + 1e-5f);
    __half* orow = out + (long long)row * DIMC;
    for (int i = threadIdx.x; i < DIMC; i += blockDim.x)
        orow[i] = __float2half_rn((xr[i] - mean) * inv * g[i] + b[i]);
}

// ---------------- shared helpers ---------------------------------------------------
#define SROWB 144

__device__ __forceinline__ void mma16(float* c, const uint32_t* a, const uint32_t* b) {
    asm volatile(
        "mma.sync.aligned.m16n8k16.row.col.f32.f16.f16.f32 "
        "{%0,%1,%2,%3}, {%4,%5,%6,%7}, {%8,%9}, {%0,%1,%2,%3};"
        : "+f"(c[0]), "+f"(c[1]), "+f"(c[2]), "+f"(c[3])
        : "r"(a[0]), "r"(a[1]), "r"(a[2]), "r"(a[3]), "r"(b[0]), "r"(b[1]));
}
__device__ __forceinline__ void cpa16(uint32_t dst, const void* src, bool pred) {
    unsigned ssz = pred ? 16u : 0u;
    asm volatile("cp.async.cg.shared.global [%0], [%1], 16, %2;"
                 :: "r"(dst), "l"(src), "r"(ssz));
}
__device__ __forceinline__ void cp_commit() { asm volatile("cp.async.commit_group;"); }

__device__ __forceinline__ void ldmA(uint32_t* a, uint32_t base, int m0, int kb, int lane) {
    uint32_t addr = base + (uint32_t)(m0 + (lane & 15)) * SROWB
                  + (uint32_t)(kb + (lane >> 4) * 8) * 2;
    asm volatile("ldmatrix.sync.aligned.m8n8.x4.shared.b16 {%0,%1,%2,%3}, [%4];"
                 : "=r"(a[0]), "=r"(a[1]), "=r"(a[2]), "=r"(a[3]) : "r"(addr));
}
__device__ __forceinline__ void ldmB2(uint32_t* b, uint32_t base, int n0, int kb, int lane) {
    uint32_t addr = base + (uint32_t)(n0 + (lane & 7) + ((lane >> 4) * 8)) * SROWB
                  + (uint32_t)(kb + ((lane >> 3) & 1) * 8) * 2;
    asm volatile("ldmatrix.sync.aligned.m8n8.x4.shared.b16 {%0,%1,%2,%3}, [%4];"
                 : "=r"(b[0]), "=r"(b[1]), "=r"(b[2]), "=r"(b[3]) : "r"(addr));
}
__device__ __forceinline__ void ldm4(uint32_t* r, uint32_t addr) {
    asm volatile("ldmatrix.sync.aligned.m8n8.x4.shared.b16 {%0,%1,%2,%3}, [%4];"
                 : "=r"(r[0]), "=r"(r[1]), "=r"(r[2]), "=r"(r[3]) : "r"(addr));
}
__device__ __forceinline__ void ldm4t(uint32_t* r, uint32_t addr) {
    asm volatile("ldmatrix.sync.aligned.m8n8.x4.trans.shared.b16 {%0,%1,%2,%3}, [%4];"
                 : "=r"(r[0]), "=r"(r[1]), "=r"(r[2]), "=r"(r[3]) : "r"(addr));
}

// ---------------- fused attention: QK^T -> split softmax -> AV ---------------------
// CTA = (64 q-rows, one (b,h)). S kept in smem fp32; fp16 copy written in place.
#define QS 64
#define SRS 2560                      // S fp32 row stride (bytes)
#define KV_STG (128*SROWB)            // 18432
#define SM_Q  0
#define SM_KV 9216
#define SM_S  46080
#define ATTN_SMEM (SM_S + QS*SRS)     // 209920

__global__ __launch_bounds__(256, 1)
void attn_fused(const __half* __restrict__ qkvh,
                float* __restrict__ out_w,
                __half* __restrict__ och) {
    extern __shared__ __align__(16) char sh[];
    uint32_t shb = (uint32_t)__cvta_generic_to_shared(sh);

    int z = blockIdx.y;
    int b = z / NHEADS, h = z % NHEADS;
    int q0 = blockIdx.x * QS;
    int tid = threadIdx.x, warp = tid >> 5, lane = tid & 31;
    int wm = warp >> 1, wn = warp & 1;
    int group = lane >> 2, tg = lane & 3;

    const __half* Qg = qkvh + (long long)(b * SEQ) * QKVC + h * HD;
    const __half* Kg = Qg + DIMC;
    const __half* Vg = Qg + 2 * DIMC;

    // issue Q + K0
    #pragma unroll
    for (int t = 0; t < 2; t++) {
        int i = tid + t * 256;
        int r = i >> 3, c = i & 7;
        int gq = q0 + r;
        cpa16(shb + SM_Q + r * SROWB + c * 16, Qg + (long long)gq * QKVC + c * 8, gq < SEQ);
    }
    #pragma unroll
    for (int t = 0; t < 4; t++) {
        int i = tid + t * 256;
        int r = i >> 3, c = i & 7;
        cpa16(shb + SM_KV + r * SROWB + c * 16, Kg + (long long)r * QKVC + c * 8, r < SEQ);
    }
    cp_commit();

    uint32_t aq[4][4];

    // ---------------- phase 1: S = Q @ K^T * 0.125 into smem fp32 ----------------
    for (int jb = 0; jb < 5; jb++) {
        if (jb < 4) {
            int s = (jb + 1) & 1;
            int kb0 = (jb + 1) * 128;
            #pragma unroll
            for (int t = 0; t < 4; t++) {
                int i = tid + t * 256;
                int r = i >> 3, c = i & 7;
                int gk = kb0 + r;
                cpa16(shb + SM_KV + s * KV_STG + r * SROWB + c * 16,
                      Kg + (long long)gk * QKVC + c * 8, gk < SEQ);
            }
            cp_commit();
            asm volatile("cp.async.wait_group 1;");
        } else {
            asm volatile("cp.async.wait_group 0;");
        }
        __syncthreads();
        if (jb == 0) {
            #pragma unroll
            for (int ks = 0; ks < 4; ks++)
                ldmA(aq[ks], shb + SM_Q, wm * 16, ks * 16, lane);
        }
        float acc[8][4];
        #pragma unroll
        for (int i = 0; i < 8; i++)
            #pragma unroll
            for (int r = 0; r < 4; r++) acc[i][r] = 0.f;

        uint32_t kbase = shb + SM_KV + (jb & 1) * KV_STG;
        #pragma unroll
        for (int ks = 0; ks < 4; ks++) {
            uint32_t bfr[8][2];
            #pragma unroll
            for (int nt = 0; nt < 8; nt += 2) {
                uint32_t bb[4];
                ldmB2(bb, kbase, wn * 64 + nt * 8, ks * 16, lane);
                bfr[nt][0] = bb[0]; bfr[nt][1] = bb[1];
                bfr[nt + 1][0] = bb[2]; bfr[nt + 1][1] = bb[3];
            }
            #pragma unroll
            for (int nt = 0; nt < 8; nt++) mma16(acc[nt], aq[ks], bfr[nt]);
        }
        #pragma unroll
        for (int nt = 0; nt < 8; nt++) {
            int col = jb * 128 + wn * 64 + nt * 8 + tg * 2;
            #pragma unroll
            for (int hf = 0; hf < 2; hf++) {
                int row = wm * 16 + group + hf * 8;
                float2 v = make_float2(acc[nt][hf * 2] * 0.125f, acc[nt][hf * 2 + 1] * 0.125f);
                *(float2*)(sh + SM_S + row * SRS + col * 4) = v;
            }
        }
        __syncthreads();
    }

    // overlap: issue V0 during softmax (stage 0 was last used by jb=4, done)
    #pragma unroll
    for (int t = 0; t < 4; t++) {
        int i = tid + t * 256;
        int r = i >> 3, c = i & 7;
        cpa16(shb + SM_KV + r * SROWB + c * 16, Vg + (long long)r * QKVC + c * 8, r < SEQ);
    }
    cp_commit();

    // ---------------- phase 2: split softmax; fp32 -> out_w, fp16 in place --------
    #pragma unroll 1
    for (int rr = 0; rr < 8; rr++) {
        int row = warp * 8 + rr;
        float v[20];
        #pragma unroll
        for (int j = 0; j < 20; j++) {
            int c = lane + j * 32;
            float f = *(const float*)(sh + SM_S + row * SRS + c * 4);
            v[j] = (c < SEQ) ? f : -1e30f;
        }
        bool in0 = lane < CLSK;
        float m0 = in0 ? v[0] : -1e30f;
        float m1 = in0 ? -1e30f : v[0];
        #pragma unroll
        for (int j = 1; j < 20; j++) m1 = fmaxf(m1, v[j]);
        #pragma unroll
        for (int o = 16; o; o >>= 1) {
            m0 = fmaxf(m0, __shfl_xor_sync(0xffffffffu, m0, o));
            m1 = fmaxf(m1, __shfl_xor_sync(0xffffffffu, m1, o));
        }
        float s0 = 0.f, s1 = 0.f;
        {
            float e = expf(v[0] - (in0 ? m0 : m1));
            v[0] = e;
            if (in0) s0 += e; else s1 += e;
        }
        #pragma unroll
        for (int j = 1; j < 20; j++) {
            int c = lane + j * 32;
            float e = (c < SEQ) ? expf(v[j] - m1) : 0.f;
            v[j] = e; s1 += e;
        }
        #pragma unroll
        for (int o = 16; o; o >>= 1) {
            s0 += __shfl_xor_sync(0xffffffffu, s0, o);
            s1 += __shfl_xor_sync(0xffffffffu, s1, o);
        }
        float r0 = 1.0f / s0, r1 = 1.0f / s1;

        int gq = q0 + row;
        bool qok = gq < SEQ;
        float* wrow = out_w + ((long long)z * SEQ + gq) * SEQ;
        __half* hrow = (__half*)(sh + SM_S + row * SRS + 16 * (row & 7));
        {
            float o0 = v[0] * (in0 ? r0 : r1);
            if (qok) wrow[lane] = o0;
            hrow[lane] = __float2half_rn(o0);
        }
        #pragma unroll
        for (int j = 1; j < 20; j++) {
            int c = lane + j * 32;
            bool cok = c < SEQ;
            float o = v[j] * r1;
            if (qok && cok) wrow[c] = o;
            hrow[c] = cok ? __float2half_rn(o) : __float2half(0.f);
        }
    }
    __syncthreads();

    // ---------------- phase 3: O = P @ V ------------------------------------------
    float oacc[4][4];
    #pragma unroll
    for (int i = 0; i < 4; i++)
        #pragma unroll
        for (int r = 0; r < 4; r++) oacc[i][r] = 0.f;

    for (int vb = 0; vb < 5; vb++) {
        if (vb < 4) {
            int s = (vb + 1) & 1;
            int v0 = (vb + 1) * 128;
            #pragma unroll
            for (int t = 0; t < 4; t++) {
                int i = tid + t * 256;
                int r = i >> 3, c = i & 7;
                int gk = v0 + r;
                cpa16(shb + SM_KV + s * KV_STG + r * SROWB + c * 16,
                      Vg + (long long)gk * QKVC + c * 8, gk < SEQ);
            }
            cp_commit();
            asm volatile("cp.async.wait_group 1;");
        } else {
            asm volatile("cp.async.wait_group 0;");
        }
        __syncthreads();
        uint32_t vbase = shb + SM_KV + (vb & 1) * KV_STG;
        #pragma unroll
        for (int ks = 0; ks < 8; ks++) {
            uint32_t a[4];
            {
                int row = wm * 16 + (lane & 15);
                int kcol = vb * 128 + ks * 16 + (lane >> 4) * 8;
                ldm4(a, shb + SM_S + row * SRS + 16 * (row & 7) + kcol * 2);
            }
            uint32_t bfr[4][2];
            #pragma unroll
            for (int nt = 0; nt < 4; nt += 2) {
                int krow = ks * 16 + (lane & 15);
                int ncol = wn * 32 + nt * 8 + ((lane >> 4) << 3);
                uint32_t bb[4];
                ldm4t(bb, vbase + krow * SROWB + ncol * 2);
                bfr[nt][0] = bb[0]; bfr[nt][1] = bb[1];
                bfr[nt + 1][0] = bb[2]; bfr[nt + 1][1] = bb[3];
            }
            #pragma unroll
            for (int nt = 0; nt < 4; nt++) mma16(oacc[nt], a, bfr[nt]);
        }
        __syncthreads();
    }

    // epilogue -> och fp16 head-concat
    #pragma unroll
    for (int nt = 0; nt < 4; nt++) {
        int col = wn * 32 + nt * 8 + tg * 2;
        #pragma unroll
        for (int hf = 0; hf < 2; hf++) {
            int row = wm * 16 + group + hf * 8;
            int gq = q0 + row;
            if (gq < SEQ) {
                __half2 hv = __floats2half2_rn(oacc[nt][hf * 2], oacc[nt][hf * 2 + 1]);
                *(__half2*)(och + (long long)(b * SEQ + gq) * DIMC + h * HD + col) = hv;
            }
        }
    }
}

// ---------------- fp16 tensor-core GEMM (TN), ldmatrix + 3-stage cp.async ----------
#define BK 64
#define NSTG 3

template<int BN_, int WNS, int MT, int NT>
__global__ __launch_bounds__(256, 2)
void gemm_h(const __half* __restrict__ A, const __half* __restrict__ B,
            const float* __restrict__ bias, const float* __restrict__ res,
            float* __restrict__ Cf, __half* __restrict__ Ch,
            int M, int Nn, int K, int lda, int ldb, int ldc,
            float alpha, int act) {
    constexpr int TILE_A = 128 * SROWB;
    constexpr int TILE_Bt = BN_ * SROWB;
    constexpr int STG = TILE_A + TILE_Bt;
    extern __shared__ __align__(16) char sh[];
    uint32_t shb = (uint32_t)__cvta_generic_to_shared(sh);

    int tid = threadIdx.x, warp = tid >> 5, lane = tid & 31;
    int wm = warp / WNS, wn = warp % WNS;
    int group = lane >> 2, tg = lane & 3;
    int row0 = blockIdx.y * 128, col0 = blockIdx.x * BN_;

    float acc[MT][NT][4];
    #pragma unroll
    for (int i = 0; i < MT; i++)
        #pragma unroll
        for (int j = 0; j < NT; j++)
            #pragma unroll
            for (int r = 0; r < 4; r++) acc[i][j][r] = 0.f;

    auto load_tiles = [&](int s, int k0) {
        uint32_t a0 = shb + s * STG;
        uint32_t b0 = a0 + TILE_A;
        #pragma unroll
        for (int t = 0; t < 4; t++) {
            int i = tid + t * 256;
            int r = i >> 3, c = i & 7;
            int gr = row0 + r;
            cpa16(a0 + r * SROWB + c * 16, A + (long long)gr * lda + k0 + c * 8, gr < M);
        }
        #pragma unroll
        for (int t = 0; t < BN_ / 32; t++) {
            int i = tid + t * 256;
            int r = i >> 3, c = i & 7;
            int gn = col0 + r;
            cpa16(b0 + r * SROWB + c * 16, B + (long long)gn * ldb + k0 + c * 8, gn < Nn);
        }
    };

    auto compute = [&](int s) {
        uint32_t a0 = shb + s * STG;
        uint32_t b0 = a0 + TILE_A;
        #pragma unroll
        for (int ks = 0; ks < 4; ks++) {
            int kb = ks * 16;
            uint32_t a[MT][4], b[NT][2];
            #pragma unroll
            for (int mt = 0; mt < MT; mt++)
                ldmA(a[mt], a0, wm * MT * 16 + mt * 16, kb, lane);
            #pragma unroll
            for (int nt = 0; nt < NT; nt += 2) {
                uint32_t bb[4];
                ldmB2(bb, b0, wn * NT * 8 + nt * 8, kb, lane);
                b[nt][0] = bb[0]; b[nt][1] = bb[1];
                b[nt + 1][0] = bb[2]; b[nt + 1][1] = bb[3];
            }
            #pragma unroll
            for (int mt = 0; mt < MT; mt++)
                #pragma unroll
                for (int nt = 0; nt < NT; nt++)
                    mma16(acc[mt][nt], a[mt], b[nt]);
        }
    };

    int nT = K / BK;
    #pragma unroll
    for (int s = 0; s < NSTG - 1; s++) {
        if (s < nT) load_tiles(s, s * BK);
        cp_commit();
    }
    for (int t = 0; t < nT; t++) {
        asm volatile("cp.async.wait_group %0;" :: "n"(NSTG - 2));
        __syncthreads();
        int pf = t + NSTG - 1;
        if (pf < nT) load_tiles(pf % NSTG, pf * BK);
        cp_commit();
        compute(t % NSTG);
    }

    #pragma unroll
    for (int mt = 0; mt < MT; mt++) {
        #pragma unroll
        for (int nt = 0; nt < NT; nt++) {
            int gc = col0 + wn * NT * 8 + nt * 8 + tg * 2;
            if (gc >= Nn) continue;
            float bx = 0.f, by = 0.f;
            if (bias) { bx = bias[gc]; by = bias[gc + 1]; }
            #pragma unroll
            for (int hf = 0; hf < 2; hf++) {
                int gm = row0 + wm * MT * 16 + mt * 16 + group + hf * 8;
                if (gm >= M) continue;
                float v0 = acc[mt][nt][hf * 2]     * alpha + bx;
                float v1 = acc[mt][nt][hf * 2 + 1] * alpha + by;
                if (act == 1) {
                    v0 = 0.5f * v0 * (1.0f + erff(v0 * 0.70710678118654752f));
                    v1 = 0.5f * v1 * (1.0f + erff(v1 * 0.70710678118654752f));
                }
                if (res) {
                    float2 rr = *(const float2*)(res + (long long)gm * ldc + gc);
                    v0 += rr.x; v1 += rr.y;
                }
                if (Cf) *(float2*)(Cf + (long long)gm * ldc + gc) = make_float2(v0, v1);
                if (Ch) *(__half2*)(Ch + (long long)gm * ldc + gc) =
                            __floats2half2_rn(v0, v1);
            }
        }
    }
}

// ---------------- host-side orchestration -------------------------------------------
extern "C" void kernel_launch(void* const* d_in, const int* in_sizes, int n_in,
                              void* d_out, int out_size) {
    const float* x      = (const float*)d_in[0];
    const float* qkv_w  = (const float*)d_in[1];
    const float* qkv_b  = (const float*)d_in[2];
    const float* proj_w = (const float*)d_in[3];
    const float* proj_b = (const float*)d_in[4];
    const float* ln1_g  = (const float*)d_in[5];
    const float* ln1_b  = (const float*)d_in[6];
    const float* ln2_g  = (const float*)d_in[7];
    const float* ln2_b  = (const float*)d_in[8];
    const float* fc1_w  = (const float*)d_in[9];
    const float* fc1_b  = (const float*)d_in[10];
    const float* fc2_w  = (const float*)d_in[11];
    const float* fc2_b  = (const float*)d_in[12];

    float* out_x = (float*)d_out;
    float* out_w = out_x + (long long)ROWS * DIMC;

    __half *h1h, *qkvh, *och, *mlph, *qkvwh, *projwh, *fc1wh, *fc2wh;
    float* x2;
    cudaGetSymbolAddress((void**)&h1h,   g_h1h);
    cudaGetSymbolAddress((void**)&qkvh,  g_qkvh);
    cudaGetSymbolAddress((void**)&och,   g_och);
    cudaGetSymbolAddress((void**)&mlph,  g_mlph);
    cudaGetSymbolAddress((void**)&x2,    g_x2);
    cudaGetSymbolAddress((void**)&qkvwh, g_qkvwh);
    cudaGetSymbolAddress((void**)&projwh,g_projwh);
    cudaGetSymbolAddress((void**)&fc1wh, g_fc1wh);
    cudaGetSymbolAddress((void**)&fc2wh, g_fc2wh);

    const int SM128 = NSTG * (128 + 128) * SROWB;   // 110592 B
    cudaFuncSetAttribute((const void*)gemm_h<128,4,4,4>,
                         cudaFuncAttributeMaxDynamicSharedMemorySize, SM128);
    cudaFuncSetAttribute((const void*)attn_fused,
                         cudaFuncAttributeMaxDynamicSharedMemorySize, ATTN_SMEM);

    f2h4<<<(QKVC * DIMC / 4 + 255) / 256, 256>>>((const float4*)qkv_w, (__half2*)qkvwh, QKVC * DIMC / 4);
    f2h4<<<(DIMC * DIMC / 4 + 255) / 256, 256>>>((const float4*)proj_w, (__half2*)projwh, DIMC * DIMC / 4);
    f2h4<<<(HIDDEN * DIMC / 4 + 255) / 256, 256>>>((const float4*)fc1_w, (__half2*)fc1wh, HIDDEN * DIMC / 4);
    f2h4<<<(DIMC * HIDDEN / 4 + 255) / 256, 256>>>((const float4*)fc2_w, (__half2*)fc2wh, DIMC * HIDDEN / 4);

    const int MB = (ROWS + 127) / 128;   // 75

    // 1. LN1 -> fp16
    ln_kernel<<<ROWS, 256>>>(x, ln1_g, ln1_b, h1h);

    // 2. QKV projection -> fp16
    gemm_h<128,4,4,4><<<dim3(QKVC / 128, MB, 1), 256, SM128>>>(
        h1h, qkvwh, qkv_b, nullptr, nullptr, qkvh,
        ROWS, QKVC, DIMC, DIMC, DIMC, QKVC, 1.0f, 0);

    // 3. fused attention: QK^T + split softmax (-> out_w) + AV (-> och)
    attn_fused<<<dim3((SEQ + QS - 1) / QS, BATCH * NHEADS), 256, ATTN_SMEM>>>(
        qkvh, out_w, och);

    // 4. proj + residual -> x2 fp32
    gemm_h<128,4,4,4><<<dim3(DIMC / 128, MB, 1), 256, SM128>>>(
        och, projwh, proj_b, x, x2, nullptr,
        ROWS, DIMC, DIMC, DIMC, DIMC, DIMC, 1.0f, 0);

    // 5. LN2 -> fp16
    ln_kernel<<<ROWS, 256>>>(x2, ln2_g, ln2_b, h1h);

    // 6. FC1 + exact GELU -> fp16
    gemm_h<128,4,4,4><<<dim3(HIDDEN / 128, MB, 1), 256, SM128>>>(
        h1h, fc1wh, fc1_b, nullptr, nullptr, mlph,
        ROWS, HIDDEN, DIMC, DIMC, DIMC, HIDDEN, 1.0f, 1);

    // 7. FC2 + residual -> final x output fp32
    gemm_h<128,4,4,4><<<dim3(DIMC / 128, MB, 1), 256, SM128>>>(
        mlph, fc2wh, fc2_b, x2, out_x, nullptr,
        ROWS, DIMC, HIDDEN, HIDDEN, HIDDEN, DIMC, 1.0f, 0);
}